// round 7
// baseline (speedup 1.0000x reference)
#include <cuda_runtime.h>
#include <math.h>

// ---------------- problem constants ----------------
#define BB   32          // batch
#define TS   64          // T_src
#define TT   64          // T_tgt
#define EE   512         // embedding dim
#define HH   512         // encoder hidden (per direction)
#define DH   1024        // decoder hidden (= 2H)
#define VV   32000       // vocab
#define KD   1536        // E + 2H (decoder input concat)
#define MOUT (BB*TT)     // 2048 output rows

// ---------------- device scratch (no allocs allowed) ----------------
__device__ float g_emb_src[TS*BB*EE];
__device__ float g_emb_tgt[TT*BB*EE];
__device__ float g_enc_out[TS*BB*DH];
__device__ float g_encproj[TS*BB*DH];
__device__ float g_hf[2][BB*HH];
__device__ float g_hb[2][BB*HH];
__device__ float g_cf[BB*HH];
__device__ float g_cb[BB*HH];
__device__ float g_dh[2][BB*DH];
__device__ float g_dc[BB*DH];
__device__ float g_hq[BB*DH];
__device__ float g_cvec[BB*DH];
__device__ float g_hs[BB*TT*DH];
__device__ float g_rowmax[MOUT];
__device__ float g_rowlse[MOUT];

// ---------------- helpers ----------------
__device__ __forceinline__ float warp_sum(float v) {
    #pragma unroll
    for (int o = 16; o; o >>= 1) v += __shfl_xor_sync(0xffffffffu, v, o);
    return v;
}
__device__ __forceinline__ float sigmoidf(float x) { return 1.f / (1.f + expf(-x)); }
__device__ __forceinline__ float dot4(float4 a, float4 b) {
    return a.x*b.x + a.y*b.y + a.z*b.z + a.w*b.w;
}

// ---------------- embedding gather (src + tgt) ----------------
__global__ void k_embed(const int* __restrict__ inp, const int* __restrict__ tar,
                        const float* __restrict__ enc_emb, const float* __restrict__ dec_emb) {
    int i = blockIdx.x * blockDim.x + threadIdx.x;     // exact grid: 2*TS*BB*EE
    const int n1 = TS * BB * EE;
    if (i < n1) {
        int t = i / (BB*EE); int r = i - t*(BB*EE); int b = r / EE; int e = r - b*EE;
        g_emb_src[i] = enc_emb[(long)inp[b*TS + t] * EE + e];
    } else {
        int j = i - n1;
        int t = j / (BB*EE); int r = j - t*(BB*EE); int b = r / EE; int e = r - b*EE;
        g_emb_tgt[j] = dec_emb[(long)tar[b*TT + t] * EE + e];
    }
}

// ---------------- zero-init encoder states ----------------
__global__ void k_init() {
    int i = blockIdx.x * blockDim.x + threadIdx.x;     // 4*BB*HH total
    const int n = BB * HH;
    if      (i <   n) g_hf[0][i]       = 0.f;
    else if (i < 2*n) g_hb[0][i - n]   = 0.f;
    else if (i < 3*n) g_cf[i - 2*n]    = 0.f;
    else              g_cb[i - 3*n]    = 0.f;
}

// ---------------- one encoder step, both directions (warp per cell) --------
__global__ void k_enc_step(const float* __restrict__ Wih_f, const float* __restrict__ Whh_f,
                           const float* __restrict__ b_f,
                           const float* __restrict__ Wih_b, const float* __restrict__ Whh_b,
                           const float* __restrict__ b_b, int t) {
    int gw   = (blockIdx.x * blockDim.x + threadIdx.x) >> 5;   // warp id, 2*BB*HH warps
    int lane = threadIdx.x & 31;
    int dir  = gw / (BB*HH);
    int rem  = gw - dir*(BB*HH);
    int b = rem / HH, j = rem % HH;
    int pos = dir ? (TS - 1 - t) : t;

    const float* Wih  = dir ? Wih_b : Wih_f;
    const float* Whh  = dir ? Whh_b : Whh_f;
    const float* bias = dir ? b_b   : b_f;
    const float* hprev = (dir ? g_hb[t & 1]       : g_hf[t & 1])       + b*HH;
    float*       hnext = (dir ? g_hb[(t+1) & 1]   : g_hf[(t+1) & 1])   + b*HH;
    float*       cbuf  = (dir ? g_cb : g_cf) + b*HH;

    const float4* x4 = (const float4*)(g_emb_src + ((long)pos*BB + b)*EE);
    const float4* w0 = (const float4*)(Wih + (0*HH + j)*EE);
    const float4* w1 = (const float4*)(Wih + (1*HH + j)*EE);
    const float4* w2 = (const float4*)(Wih + (2*HH + j)*EE);
    const float4* w3 = (const float4*)(Wih + (3*HH + j)*EE);
    float a0 = 0.f, a1 = 0.f, a2 = 0.f, a3 = 0.f;
    #pragma unroll
    for (int q = lane; q < EE/4; q += 32) {
        float4 xv = x4[q];
        a0 += dot4(xv, w0[q]); a1 += dot4(xv, w1[q]);
        a2 += dot4(xv, w2[q]); a3 += dot4(xv, w3[q]);
    }
    const float4* h4 = (const float4*)hprev;
    const float4* u0 = (const float4*)(Whh + (0*HH + j)*HH);
    const float4* u1 = (const float4*)(Whh + (1*HH + j)*HH);
    const float4* u2 = (const float4*)(Whh + (2*HH + j)*HH);
    const float4* u3 = (const float4*)(Whh + (3*HH + j)*HH);
    #pragma unroll
    for (int q = lane; q < HH/4; q += 32) {
        float4 hv = h4[q];
        a0 += dot4(hv, u0[q]); a1 += dot4(hv, u1[q]);
        a2 += dot4(hv, u2[q]); a3 += dot4(hv, u3[q]);
    }
    a0 = warp_sum(a0); a1 = warp_sum(a1); a2 = warp_sum(a2); a3 = warp_sum(a3);
    if (lane == 0) {
        float ig = sigmoidf(a0 + bias[0*HH + j]);
        float fg = sigmoidf(a1 + bias[1*HH + j]);
        float gg = tanhf  (a2 + bias[2*HH + j]);
        float og = sigmoidf(a3 + bias[3*HH + j]);
        float c  = fg * cbuf[j] + ig * gg;
        cbuf[j]  = c;
        float h  = og * tanhf(c);
        hnext[j] = h;
        g_enc_out[((long)pos*BB + b)*DH + dir*HH + j] = h;
    }
}

// ---------------- decoder init: concat encoder final states ----------------
__global__ void k_dec_init() {
    int i = blockIdx.x * blockDim.x + threadIdx.x;   // BB*DH
    int b = i / DH, o = i % DH;
    const int fin = TS & 1;                          // final state buffer index (=0)
    float h, c;
    if (o < HH) { h = g_hf[fin][b*HH + o];      c = g_cf[b*HH + o]; }
    else        { h = g_hb[fin][b*HH + o - HH]; c = g_cb[b*HH + o - HH]; }
    g_dh[0][i] = h;
    g_dc[i]    = c;
}

// ---------------- generic tiled SGEMM: C[M,N] = A[M,K] * B[N,K]^T (+bias,relu)
// 128x128 block tile, K-step 8, 8x8 per thread, 256 threads.
// Requires M%128==0, N%128==0, K%8==0, 16B-aligned rows.
__global__ void sgemm_abt(const float* __restrict__ A, int lda,
                          const float* __restrict__ B, int ldb,
                          const float* __restrict__ bias,
                          float* __restrict__ C, int ldc,
                          int K, int do_relu) {
    __shared__ float As[8][128];
    __shared__ float Bs[8][128];
    int bm = blockIdx.y, bn = blockIdx.x;
    int tid = threadIdx.x;
    int tx = tid % 16, ty = tid / 16;
    int lrow = tid >> 1;            // 0..127
    int lcol = (tid & 1) * 4;       // 0 or 4
    const float* Ab = A + ((long)bm*128 + lrow) * lda;
    const float* Bb = B + ((long)bn*128 + lrow) * ldb;

    float acc[8][8];
    #pragma unroll
    for (int r = 0; r < 8; r++)
        #pragma unroll
        for (int c = 0; c < 8; c++) acc[r][c] = 0.f;

    for (int k0 = 0; k0 < K; k0 += 8) {
        float4 av = *(const float4*)(Ab + k0 + lcol);
        float4 bv = *(const float4*)(Bb + k0 + lcol);
        As[lcol+0][lrow] = av.x; As[lcol+1][lrow] = av.y;
        As[lcol+2][lrow] = av.z; As[lcol+3][lrow] = av.w;
        Bs[lcol+0][lrow] = bv.x; Bs[lcol+1][lrow] = bv.y;
        Bs[lcol+2][lrow] = bv.z; Bs[lcol+3][lrow] = bv.w;
        __syncthreads();
        #pragma unroll
        for (int kk = 0; kk < 8; kk++) {
            float a8[8], b8[8];
            #pragma unroll
            for (int r = 0; r < 8; r++) a8[r] = As[kk][ty*8 + r];
            #pragma unroll
            for (int c = 0; c < 8; c++) b8[c] = Bs[kk][tx*8 + c];
            #pragma unroll
            for (int r = 0; r < 8; r++)
                #pragma unroll
                for (int c = 0; c < 8; c++) acc[r][c] += a8[r] * b8[c];
        }
        __syncthreads();
    }
    #pragma unroll
    for (int r = 0; r < 8; r++) {
        long m = (long)bm*128 + ty*8 + r;
        #pragma unroll
        for (int c = 0; c < 8; c++) {
            int n = bn*128 + tx*8 + c;
            float v = acc[r][c];
            if (bias) v += bias[n];
            if (do_relu) v = fmaxf(v, 0.f);
            C[m*ldc + n] = v;
        }
    }
}

// ---------------- decoder: hq = h @ Wa1^T (warp per output) ----------------
__global__ void k_hq(const float* __restrict__ Wa, int t) {
    int gw   = (blockIdx.x * blockDim.x + threadIdx.x) >> 5;  // BB*DH warps
    int lane = threadIdx.x & 31;
    int b = gw / DH, o = gw % DH;
    const float4* h4 = (const float4*)(g_dh[t & 1] + b*DH);
    const float4* w4 = (const float4*)(Wa + (long)o * (2*DH));  // Wa row, first DH cols
    float a = 0.f;
    #pragma unroll
    for (int q = lane; q < DH/4; q += 32) a += dot4(h4[q], w4[q]);
    a = warp_sum(a);
    if (lane == 0) g_hq[b*DH + o] = a;
}

// ---------------- decoder attention: scores, softmax, context -------------
__global__ void k_attn(const float* __restrict__ va) {
    __shared__ float s_hq[DH];
    __shared__ float s_sc[TS];
    __shared__ float s_inv;
    int b = blockIdx.x, tid = threadIdx.x;
    for (int o = tid; o < DH; o += 256) s_hq[o] = g_hq[b*DH + o];
    __syncthreads();
    int w = tid >> 5, lane = tid & 31;
    for (int ts = w; ts < TS; ts += 8) {
        const float* ep = g_encproj + ((long)ts*BB + b)*DH;
        float s = 0.f;
        for (int o = lane; o < DH; o += 32) s += va[o] * tanhf(s_hq[o] + ep[o]);
        s = warp_sum(s);
        if (lane == 0) s_sc[ts] = s;
    }
    __syncthreads();
    if (tid == 0) {
        float m = -1e30f;
        for (int i = 0; i < TS; i++) m = fmaxf(m, s_sc[i]);
        float s = 0.f;
        for (int i = 0; i < TS; i++) { float e = expf(s_sc[i] - m); s_sc[i] = e; s += e; }
        s_inv = 1.f / s;
    }
    __syncthreads();
    float inv = s_inv;
    for (int o = tid; o < DH; o += 256) {
        float acc = 0.f;
        #pragma unroll 4
        for (int ts = 0; ts < TS; ts++) acc += s_sc[ts] * g_enc_out[((long)ts*BB + b)*DH + o];
        g_cvec[b*DH + o] = acc * inv;
    }
}

// ---------------- decoder LSTMCell step (warp per cell) ----------------
__global__ void k_dec_lstm(const float* __restrict__ Wih_d, const float* __restrict__ Whh_d,
                           const float* __restrict__ b_d, int t) {
    int gw   = (blockIdx.x * blockDim.x + threadIdx.x) >> 5;  // BB*DH warps
    int lane = threadIdx.x & 31;
    int b = gw / DH, j = gw % DH;

    const float4* x4 = (const float4*)(g_emb_tgt + ((long)t*BB + b)*EE);
    const float4* v4 = (const float4*)(g_cvec + b*DH);
    const float4* h4 = (const float4*)(g_dh[t & 1] + b*DH);

    const float* wr0 = Wih_d + (long)(0*DH + j)*KD;
    const float* wr1 = Wih_d + (long)(1*DH + j)*KD;
    const float* wr2 = Wih_d + (long)(2*DH + j)*KD;
    const float* wr3 = Wih_d + (long)(3*DH + j)*KD;
    float a0 = 0.f, a1 = 0.f, a2 = 0.f, a3 = 0.f;
    #pragma unroll
    for (int q = lane; q < EE/4; q += 32) {
        float4 xv = x4[q];
        a0 += dot4(xv, ((const float4*)wr0)[q]); a1 += dot4(xv, ((const float4*)wr1)[q]);
        a2 += dot4(xv, ((const float4*)wr2)[q]); a3 += dot4(xv, ((const float4*)wr3)[q]);
    }
    #pragma unroll
    for (int q = lane; q < DH/4; q += 32) {
        float4 cv = v4[q];
        a0 += dot4(cv, ((const float4*)(wr0 + EE))[q]); a1 += dot4(cv, ((const float4*)(wr1 + EE))[q]);
        a2 += dot4(cv, ((const float4*)(wr2 + EE))[q]); a3 += dot4(cv, ((const float4*)(wr3 + EE))[q]);
    }
    const float4* u0 = (const float4*)(Whh_d + (long)(0*DH + j)*DH);
    const float4* u1 = (const float4*)(Whh_d + (long)(1*DH + j)*DH);
    const float4* u2 = (const float4*)(Whh_d + (long)(2*DH + j)*DH);
    const float4* u3 = (const float4*)(Whh_d + (long)(3*DH + j)*DH);
    #pragma unroll
    for (int q = lane; q < DH/4; q += 32) {
        float4 hv = h4[q];
        a0 += dot4(hv, u0[q]); a1 += dot4(hv, u1[q]);
        a2 += dot4(hv, u2[q]); a3 += dot4(hv, u3[q]);
    }
    a0 = warp_sum(a0); a1 = warp_sum(a1); a2 = warp_sum(a2); a3 = warp_sum(a3);
    if (lane == 0) {
        float ig = sigmoidf(a0 + b_d[0*DH + j]);
        float fg = sigmoidf(a1 + b_d[1*DH + j]);
        float gg = tanhf  (a2 + b_d[2*DH + j]);
        float og = sigmoidf(a3 + b_d[3*DH + j]);
        float c  = fg * g_dc[b*DH + j] + ig * gg;
        g_dc[b*DH + j] = c;
        float h  = og * tanhf(c);
        g_dh[(t+1) & 1][b*DH + j] = h;
        g_hs[((long)b*TT + t)*DH + j] = h;   // [B, T, 2H] row-major
    }
}

// ---------------- per-row max / logsumexp (online, one pass) ----------------
__device__ __forceinline__ void ms_combine(float& m, float& s, float m2, float s2) {
    float M = fmaxf(m, m2);
    s = s * expf(m - M) + s2 * expf(m2 - M);
    m = M;
}
__global__ void k_row_reduce(const float* __restrict__ C) {
    __shared__ float sm[8], ss[8];
    int row = blockIdx.x, tid = threadIdx.x;
    const float* p = C + (long)row * VV;
    float m = -1e30f, s = 0.f;
    for (int n = tid; n < VV; n += 256) {
        float x = p[n];
        float M = fmaxf(m, x);
        s = s * expf(m - M) + expf(x - M);
        m = M;
    }
    #pragma unroll
    for (int o = 16; o; o >>= 1) {
        float m2 = __shfl_xor_sync(0xffffffffu, m, o);
        float s2 = __shfl_xor_sync(0xffffffffu, s, o);
        ms_combine(m, s, m2, s2);
    }
    int w = tid >> 5;
    if ((tid & 31) == 0) { sm[w] = m; ss[w] = s; }
    __syncthreads();
    if (tid == 0) {
        m = sm[0]; s = ss[0];
        for (int i = 1; i < 8; i++) ms_combine(m, s, sm[i], ss[i]);
        g_rowmax[row] = m;
        g_rowlse[row] = logf(s);
    }
}

// ---------------- apply log_softmax in place (float4) ----------------
__global__ void k_lsm(float* __restrict__ C) {
    long i = (long)blockIdx.x * blockDim.x + threadIdx.x;   // float4 index, exact grid
    int row = (int)(i / (VV/4));
    float sub = g_rowmax[row] + g_rowlse[row];
    float4* p = (float4*)C;
    float4 v = p[i];
    v.x -= sub; v.y -= sub; v.z -= sub; v.w -= sub;
    p[i] = v;
}

// ---------------- launch ----------------
extern "C" void kernel_launch(void* const* d_in, const int* in_sizes, int n_in,
                              void* d_out, int out_size) {
    const int*   inp     = (const int*)  d_in[0];
    const int*   tar     = (const int*)  d_in[1];
    const float* enc_emb = (const float*)d_in[2];
    const float* dec_emb = (const float*)d_in[3];
    const float* Wih_f   = (const float*)d_in[4];
    const float* Whh_f   = (const float*)d_in[5];
    const float* b_f     = (const float*)d_in[6];
    const float* Wih_b   = (const float*)d_in[7];
    const float* Whh_b   = (const float*)d_in[8];
    const float* b_b     = (const float*)d_in[9];
    const float* Wa      = (const float*)d_in[10];
    const float* va      = (const float*)d_in[11];
    const float* Wih_d   = (const float*)d_in[12];
    const float* Whh_d   = (const float*)d_in[13];
    const float* b_d     = (const float*)d_in[14];
    const float* Wout    = (const float*)d_in[15];
    const float* bout    = (const float*)d_in[16];
    float* out = (float*)d_out;

    static float *sp_enc_out = nullptr, *sp_encproj = nullptr, *sp_hs = nullptr;
    if (!sp_enc_out) {
        cudaGetSymbolAddress((void**)&sp_enc_out, g_enc_out);
        cudaGetSymbolAddress((void**)&sp_encproj, g_encproj);
        cudaGetSymbolAddress((void**)&sp_hs, g_hs);
    }

    // embeddings + state init
    k_embed<<<(2*TS*BB*EE)/256, 256>>>(inp, tar, enc_emb, dec_emb);
    k_init<<<(4*BB*HH)/256, 256>>>();

    // encoder BiLSTM, 64 steps
    for (int t = 0; t < TS; t++)
        k_enc_step<<<(2*BB*HH*32)/256, 256>>>(Wih_f, Whh_f, b_f, Wih_b, Whh_b, b_b, t);

    // decoder init + attention precompute: enc_proj = enc_out @ Wa[:,DH:]^T
    k_dec_init<<<(BB*DH)/256, 256>>>();
    sgemm_abt<<<dim3(DH/128, (TS*BB)/128), 256>>>(sp_enc_out, DH, Wa + DH, 2*DH,
                                                  nullptr, sp_encproj, DH, DH, 0);

    // decoder, 64 steps
    for (int t = 0; t < TT; t++) {
        k_hq<<<(BB*DH*32)/256, 256>>>(Wa, t);
        k_attn<<<BB, 256>>>(va);
        k_dec_lstm<<<(BB*DH*32)/256, 256>>>(Wih_d, Whh_d, b_d, t);
    }

    // output projection + relu, then log_softmax
    sgemm_abt<<<dim3(VV/128, MOUT/128), 256>>>(sp_hs, DH, Wout, DH, bout, out, VV, DH, 1);
    k_row_reduce<<<MOUT, 256>>>(out);
    k_lsm<<<(int)(((long)MOUT*VV/4)/256), 256>>>(out);
}

// round 9
// speedup vs baseline: 1.1962x; 1.1962x over previous
#include <cuda_runtime.h>
#include <math.h>

// ---------------- problem constants ----------------
#define BB   32          // batch
#define TS   64          // T_src
#define TT   64          // T_tgt
#define EE   512         // embedding dim
#define HH   512         // encoder hidden (per direction)
#define DH   1024        // decoder hidden (= 2H)
#define VV   32000       // vocab
#define KD   1536        // E + 2H (decoder input concat)
#define MOUT (BB*TT)     // 2048 output rows

#define S_ENC 8          // K-splits encoder (K = 512+512 = 1024)
#define S_HQ  8          // K-splits hq      (K = 1024)
#define S_DEC 20         // K-splits decoder (K = 512+1024+1024 = 2560)

typedef unsigned long long u64;

// ---------------- device scratch (no allocs allowed) ----------------
__device__ float g_emb_src[TS*BB*EE];
__device__ float g_emb_tgt[TT*BB*EE];
__device__ float g_enc_out[TS*BB*DH];
__device__ float g_encproj[TS*BB*DH];
__device__ float g_hf[2][BB*HH];
__device__ float g_hb[2][BB*HH];
__device__ float g_cf[BB*HH];
__device__ float g_cb[BB*HH];
__device__ float g_dh[2][BB*DH];
__device__ float g_dc[BB*DH];
__device__ float g_cvec[BB*DH];
__device__ float g_hs[BB*TT*DH];
__device__ float g_rowmax[MOUT];
__device__ float g_rowlse[MOUT];
// K-split partial accumulators (gate rows are 4*H wide!)
__device__ float g_pe[2][S_ENC][BB][4*HH];   // encoder gates partials (2048 cols)
__device__ float g_ph[S_HQ][BB][DH];         // hq partials            (1024 cols)
__device__ float g_pd[S_DEC][BB][4*DH];      // decoder gates partials (4096 cols)

// ---------------- helpers ----------------
__device__ __forceinline__ float warp_sum(float v) {
    #pragma unroll
    for (int o = 16; o; o >>= 1) v += __shfl_xor_sync(0xffffffffu, v, o);
    return v;
}
__device__ __forceinline__ float sigmoidf(float x) { return 1.f / (1.f + expf(-x)); }

// packed fp32x2 FMA (Blackwell FFMA2 — double-rate fp32)
__device__ __forceinline__ u64 fma2(u64 a, u64 b, u64 c) {
    u64 d;
    asm("fma.rn.f32x2 %0, %1, %2, %3;" : "=l"(d) : "l"(a), "l"(b), "l"(c));
    return d;
}
__device__ __forceinline__ u64 dup2f(float a) {
    u64 d;
    asm("mov.b64 %0, {%1, %1};" : "=l"(d) : "f"(a));
    return d;
}
__device__ __forceinline__ float2 unpack2(u64 v) {
    float2 r;
    asm("mov.b64 {%0, %1}, %2;" : "=f"(r.x), "=f"(r.y) : "l"(v));
    return r;
}

// ---------------- embedding gather (src + tgt) ----------------
__global__ void k_embed(const int* __restrict__ inp, const int* __restrict__ tar,
                        const float* __restrict__ enc_emb, const float* __restrict__ dec_emb) {
    int i = blockIdx.x * blockDim.x + threadIdx.x;     // exact grid: 2*TS*BB*EE
    const int n1 = TS * BB * EE;
    if (i < n1) {
        int t = i / (BB*EE); int r = i - t*(BB*EE); int b = r / EE; int e = r - b*EE;
        g_emb_src[i] = enc_emb[(long)inp[b*TS + t] * EE + e];
    } else {
        int j = i - n1;
        int t = j / (BB*EE); int r = j - t*(BB*EE); int b = r / EE; int e = r - b*EE;
        g_emb_tgt[j] = dec_emb[(long)tar[b*TT + t] * EE + e];
    }
}

// ---------------- zero-init encoder states ----------------
__global__ void k_init() {
    int i = blockIdx.x * blockDim.x + threadIdx.x;     // 4*BB*HH total
    const int n = BB * HH;
    if      (i <   n) g_hf[0][i]       = 0.f;
    else if (i < 2*n) g_hb[0][i - n]   = 0.f;
    else if (i < 3*n) g_cf[i - 2*n]    = 0.f;
    else              g_cb[i - 3*n]    = 0.f;
}

// =====================================================================
// gemm32 core: C_tile[32, 256] += X[32, 16k] @ W[256 cols, 16k]^T
// 256 threads: tx = tid&31 (8 cols each), ty = tid>>5 (4 rows each).
// FFMA2 inner: W col-pairs read packed from smem, X rows duplicated.
// X, W already offset to the k-tile start.
// =====================================================================
__device__ __forceinline__ void g32_tile(const float* __restrict__ X, int xld,
                                         const float* __restrict__ W, int wld, int colbase,
                                         float Ws[16][260], float Xs[16][36],
                                         u64 acc[4][4], int tid, int tx, int ty)
{
    // load W tile: 256 cols x 16 k (1024 float4)
    #pragma unroll
    for (int u = 0; u < 4; u++) {
        int idx = tid + u*256;
        int col = idx >> 2, kc = (idx & 3) * 4;
        float4 w = *(const float4*)(W + (long)(colbase + col)*wld + kc);
        Ws[kc+0][col] = w.x; Ws[kc+1][col] = w.y; Ws[kc+2][col] = w.z; Ws[kc+3][col] = w.w;
    }
    // load X tile: 32 rows x 16 k (128 float4)
    if (tid < 128) {
        int row = tid >> 2, kc = (tid & 3) * 4;
        float4 x = *(const float4*)(X + (long)row*xld + kc);
        Xs[kc+0][row] = x.x; Xs[kc+1][row] = x.y; Xs[kc+2][row] = x.z; Xs[kc+3][row] = x.w;
    }
    __syncthreads();
    #pragma unroll
    for (int kk = 0; kk < 16; kk++) {
        ulonglong2 w0 = *(const ulonglong2*)&Ws[kk][tx*8];
        ulonglong2 w1 = *(const ulonglong2*)&Ws[kk][tx*8 + 4];
        float4 xv = *(const float4*)&Xs[kk][ty*4];
        u64 a;
        a = dup2f(xv.x);
        acc[0][0] = fma2(a, w0.x, acc[0][0]); acc[0][1] = fma2(a, w0.y, acc[0][1]);
        acc[0][2] = fma2(a, w1.x, acc[0][2]); acc[0][3] = fma2(a, w1.y, acc[0][3]);
        a = dup2f(xv.y);
        acc[1][0] = fma2(a, w0.x, acc[1][0]); acc[1][1] = fma2(a, w0.y, acc[1][1]);
        acc[1][2] = fma2(a, w1.x, acc[1][2]); acc[1][3] = fma2(a, w1.y, acc[1][3]);
        a = dup2f(xv.z);
        acc[2][0] = fma2(a, w0.x, acc[2][0]); acc[2][1] = fma2(a, w0.y, acc[2][1]);
        acc[2][2] = fma2(a, w1.x, acc[2][2]); acc[2][3] = fma2(a, w1.y, acc[2][3]);
        a = dup2f(xv.w);
        acc[3][0] = fma2(a, w0.x, acc[3][0]); acc[3][1] = fma2(a, w0.y, acc[3][1]);
        acc[3][2] = fma2(a, w1.x, acc[3][2]); acc[3][3] = fma2(a, w1.y, acc[3][3]);
    }
    __syncthreads();
}

__device__ __forceinline__ void g32_store(float* out, int ldc, int colbase,
                                          u64 acc[4][4], int tx, int ty)
{
    #pragma unroll
    for (int r = 0; r < 4; r++) {
        int b = ty*4 + r;
        #pragma unroll
        for (int cp = 0; cp < 4; cp++) {
            float2 v = unpack2(acc[r][cp]);
            *(float2*)(out + (long)b*ldc + colbase + tx*8 + cp*2) = v;
        }
    }
}

// ---------------- encoder step gates: both dirs, K-split ----------------
// grid (8, S_ENC, 2): x = 256-col tile of 2048 gate cols, y = k-split, z = dir
__global__ void k_enc_gemm(const float* __restrict__ Wih_f, const float* __restrict__ Whh_f,
                           const float* __restrict__ Wih_b, const float* __restrict__ Whh_b,
                           int t) {
    __shared__ __align__(16) float Ws[16][260];
    __shared__ __align__(16) float Xs[16][36];
    int tid = threadIdx.x, tx = tid & 31, ty = tid >> 5;
    int colbase = blockIdx.x * 256;
    int sp  = blockIdx.y;
    int dir = blockIdx.z;
    int pos = dir ? (TS-1-t) : t;
    const float* Wih = dir ? Wih_b : Wih_f;
    const float* Whh = dir ? Whh_b : Whh_f;
    const float* Xe  = g_emb_src + (long)pos*BB*EE;
    const float* Xh  = dir ? g_hb[t & 1] : g_hf[t & 1];

    u64 acc[4][4];
    #pragma unroll
    for (int r = 0; r < 4; r++)
        #pragma unroll
        for (int c = 0; c < 4; c++) acc[r][c] = 0ull;

    int k0 = sp * 128;   // K total = 1024 (512 emb + 512 h)
    #pragma unroll
    for (int kt = 0; kt < 8; kt++) {
        int kg = k0 + kt*16;
        if (kg < 512) g32_tile(Xe + kg,       EE, Wih + kg,       EE, colbase, Ws, Xs, acc, tid, tx, ty);
        else          g32_tile(Xh + (kg-512), HH, Whh + (kg-512), HH, colbase, Ws, Xs, acc, tid, tx, ty);
    }
    g32_store(&g_pe[dir][sp][0][0], 4*HH, colbase, acc, tx, ty);
}

// ---------------- encoder pointwise: combine partials + LSTM cell ----------
__global__ void k_enc_point(const float* __restrict__ b_f, const float* __restrict__ b_b, int t) {
    int i = blockIdx.x * blockDim.x + threadIdx.x;   // 2*BB*HH
    int dir = i / (BB*HH);
    int rem = i - dir*(BB*HH);
    int b = rem / HH, j = rem % HH;
    const float* bias = dir ? b_b : b_f;
    float g0 = bias[0*HH + j], g1 = bias[1*HH + j], g2 = bias[2*HH + j], g3 = bias[3*HH + j];
    #pragma unroll
    for (int s = 0; s < S_ENC; s++) {
        const float* p = &g_pe[dir][s][b][0];       // row width 4*HH
        g0 += p[0*HH + j]; g1 += p[1*HH + j]; g2 += p[2*HH + j]; g3 += p[3*HH + j];
    }
    float* cbuf = (dir ? g_cb : g_cf) + b*HH;
    float c = sigmoidf(g1) * cbuf[j] + sigmoidf(g0) * tanhf(g2);
    cbuf[j] = c;
    float h = sigmoidf(g3) * tanhf(c);
    ((dir ? g_hb[(t+1) & 1] : g_hf[(t+1) & 1]) + b*HH)[j] = h;
    int pos = dir ? (TS-1-t) : t;
    g_enc_out[((long)pos*BB + b)*DH + dir*HH + j] = h;
}

// ---------------- decoder init: concat encoder final states ----------------
__global__ void k_dec_init() {
    int i = blockIdx.x * blockDim.x + threadIdx.x;   // BB*DH
    int b = i / DH, o = i % DH;
    const int fin = TS & 1;                          // = 0
    float h, c;
    if (o < HH) { h = g_hf[fin][b*HH + o];      c = g_cf[b*HH + o]; }
    else        { h = g_hb[fin][b*HH + o - HH]; c = g_cb[b*HH + o - HH]; }
    g_dh[0][i] = h;
    g_dc[i]    = c;
}

// ---------------- hq = h @ Wa[:, :DH]^T, K-split ----------------
// grid (4, S_HQ)
__global__ void k_hq_gemm(const float* __restrict__ Wa, int t) {
    __shared__ __align__(16) float Ws[16][260];
    __shared__ __align__(16) float Xs[16][36];
    int tid = threadIdx.x, tx = tid & 31, ty = tid >> 5;
    int colbase = blockIdx.x * 256;
    int sp = blockIdx.y;
    const float* Xh = g_dh[t & 1];

    u64 acc[4][4];
    #pragma unroll
    for (int r = 0; r < 4; r++)
        #pragma unroll
        for (int c = 0; c < 4; c++) acc[r][c] = 0ull;

    int k0 = sp * 128;  // K = 1024
    #pragma unroll
    for (int kt = 0; kt < 8; kt++) {
        int kg = k0 + kt*16;
        g32_tile(Xh + kg, DH, Wa + kg, 2*DH, colbase, Ws, Xs, acc, tid, tx, ty);
    }
    g32_store(&g_ph[sp][0][0], DH, colbase, acc, tx, ty);
}

// ---------------- decoder attention: scores, softmax, context -------------
__global__ void k_attn(const float* __restrict__ va) {
    __shared__ float s_hq[DH];
    __shared__ float s_sc[TS];
    __shared__ float s_inv;
    int b = blockIdx.x, tid = threadIdx.x;
    for (int o = tid; o < DH; o += 256) {
        float v = 0.f;
        #pragma unroll
        for (int s = 0; s < S_HQ; s++) v += g_ph[s][b][o];
        s_hq[o] = v;
    }
    __syncthreads();
    int w = tid >> 5, lane = tid & 31;
    for (int ts = w; ts < TS; ts += 8) {
        const float* ep = g_encproj + ((long)ts*BB + b)*DH;
        float s = 0.f;
        for (int o = lane; o < DH; o += 32) s += va[o] * tanhf(s_hq[o] + ep[o]);
        s = warp_sum(s);
        if (lane == 0) s_sc[ts] = s;
    }
    __syncthreads();
    if (tid == 0) {
        float m = -1e30f;
        for (int i = 0; i < TS; i++) m = fmaxf(m, s_sc[i]);
        float s = 0.f;
        for (int i = 0; i < TS; i++) { float e = expf(s_sc[i] - m); s_sc[i] = e; s += e; }
        s_inv = 1.f / s;
    }
    __syncthreads();
    float inv = s_inv;
    for (int o = tid; o < DH; o += 256) {
        float acc = 0.f;
        #pragma unroll 4
        for (int ts = 0; ts < TS; ts++) acc += s_sc[ts] * g_enc_out[((long)ts*BB + b)*DH + o];
        g_cvec[b*DH + o] = acc * inv;
    }
}

// ---------------- decoder gates: K-split over [emb | cvec | h] -------------
// grid (16, S_DEC): K = 2560 = 512 emb + 1024 cvec + 1024 h
__global__ void k_dec_gemm(const float* __restrict__ Wih_d, const float* __restrict__ Whh_d,
                           int t) {
    __shared__ __align__(16) float Ws[16][260];
    __shared__ __align__(16) float Xs[16][36];
    int tid = threadIdx.x, tx = tid & 31, ty = tid >> 5;
    int colbase = blockIdx.x * 256;
    int sp = blockIdx.y;
    const float* Xe = g_emb_tgt + (long)t*BB*EE;
    const float* Xh = g_dh[t & 1];

    u64 acc[4][4];
    #pragma unroll
    for (int r = 0; r < 4; r++)
        #pragma unroll
        for (int c = 0; c < 4; c++) acc[r][c] = 0ull;

    int k0 = sp * 128;
    #pragma unroll
    for (int kt = 0; kt < 8; kt++) {
        int kg = k0 + kt*16;
        if      (kg < 512)  g32_tile(Xe + kg,           EE, Wih_d + kg,        KD, colbase, Ws, Xs, acc, tid, tx, ty);
        else if (kg < 1536) g32_tile(g_cvec + (kg-512), DH, Wih_d + kg,        KD, colbase, Ws, Xs, acc, tid, tx, ty);
        else                g32_tile(Xh + (kg-1536),    DH, Whh_d + (kg-1536), DH, colbase, Ws, Xs, acc, tid, tx, ty);
    }
    g32_store(&g_pd[sp][0][0], 4*DH, colbase, acc, tx, ty);
}

// ---------------- decoder pointwise: combine partials + LSTM cell ----------
__global__ void k_dec_point(const float* __restrict__ b_d, int t) {
    int i = blockIdx.x * blockDim.x + threadIdx.x;   // BB*DH
    int b = i / DH, j = i % DH;
    float g0 = b_d[0*DH + j], g1 = b_d[1*DH + j], g2 = b_d[2*DH + j], g3 = b_d[3*DH + j];
    #pragma unroll
    for (int s = 0; s < S_DEC; s++) {
        const float* p = &g_pd[s][b][0];
        g0 += p[0*DH + j]; g1 += p[1*DH + j]; g2 += p[2*DH + j]; g3 += p[3*DH + j];
    }
    float c = sigmoidf(g1) * g_dc[i] + sigmoidf(g0) * tanhf(g2);
    g_dc[i] = c;
    float h = sigmoidf(g3) * tanhf(c);
    g_dh[(t+1) & 1][i] = h;
    g_hs[((long)b*TT + t)*DH + j] = h;
}

// ---------------- tiled SGEMM (FFMA2): C[M,N] = A[M,K] @ B[N,K]^T (+bias,relu)
// 128x128 tile, K-step 8, 8x8 per thread via f32x2 packed FMA, 256 threads.
__global__ void sgemm_abt(const float* __restrict__ A, int lda,
                          const float* __restrict__ B, int ldb,
                          const float* __restrict__ bias,
                          float* __restrict__ C, int ldc,
                          int K, int do_relu) {
    __shared__ __align__(16) float As[8][128];
    __shared__ __align__(16) float Bs[8][128];
    int bm = blockIdx.y, bn = blockIdx.x;
    int tid = threadIdx.x;
    int tx = tid % 16, ty = tid / 16;
    int lrow = tid >> 1;            // 0..127
    int lcol = (tid & 1) * 4;       // 0 or 4
    const float* Ab = A + ((long)bm*128 + lrow) * lda;
    const float* Bb = B + ((long)bn*128 + lrow) * ldb;

    u64 acc2[8][4];
    #pragma unroll
    for (int r = 0; r < 8; r++)
        #pragma unroll
        for (int c = 0; c < 4; c++) acc2[r][c] = 0ull;

    for (int k0 = 0; k0 < K; k0 += 8) {
        float4 av = *(const float4*)(Ab + k0 + lcol);
        float4 bv = *(const float4*)(Bb + k0 + lcol);
        As[lcol+0][lrow] = av.x; As[lcol+1][lrow] = av.y;
        As[lcol+2][lrow] = av.z; As[lcol+3][lrow] = av.w;
        Bs[lcol+0][lrow] = bv.x; Bs[lcol+1][lrow] = bv.y;
        Bs[lcol+2][lrow] = bv.z; Bs[lcol+3][lrow] = bv.w;
        __syncthreads();
        #pragma unroll
        for (int kk = 0; kk < 8; kk++) {
            float4 a0 = *(const float4*)&As[kk][ty*8];
            float4 a1 = *(const float4*)&As[kk][ty*8 + 4];
            ulonglong2 b0 = *(const ulonglong2*)&Bs[kk][tx*8];
            ulonglong2 b1 = *(const ulonglong2*)&Bs[kk][tx*8 + 4];
            u64 a;
            a = dup2f(a0.x);
            acc2[0][0]=fma2(a,b0.x,acc2[0][0]); acc2[0][1]=fma2(a,b0.y,acc2[0][1]);
            acc2[0][2]=fma2(a,b1.x,acc2[0][2]); acc2[0][3]=fma2(a,b1.y,acc2[0][3]);
            a = dup2f(a0.y);
            acc2[1][0]=fma2(a,b0.x,acc2[1][0]); acc2[1][1]=fma2(a,b0.y,acc2[1][1]);
            acc2[1][2]=fma2(a,b1.x,acc2[1][2]); acc2[1][3]=fma2(a,b1.y,acc2[1][3]);
            a = dup2f(a0.z);
            acc2[2][0]=fma2(a,b0.x,acc2[2][0]); acc2[2][1]=fma2(a,b0.y,acc2[2][1]);
            acc2[2][2]=fma2(a,b1.x,acc2[2][2]); acc2[2][3]=fma2(a,b1.y,acc2[2][3]);
            a = dup2f(a0.w);
            acc2[3][0]=fma2(a,b0.x,acc2[3][0]); acc2[3][1]=fma2(a,b0.y,acc2[3][1]);
            acc2[3][2]=fma2(a,b1.x,acc2[3][2]); acc2[3][3]=fma2(a,b1.y,acc2[3][3]);
            a = dup2f(a1.x);
            acc2[4][0]=fma2(a,b0.x,acc2[4][0]); acc2[4][1]=fma2(a,b0.y,acc2[4][1]);
            acc2[4][2]=fma2(a,b1.x,acc2[4][2]); acc2[4][3]=fma2(a,b1.y,acc2[4][3]);
            a = dup2f(a1.y);
            acc2[5][0]=fma2(a,b0.x,acc2[5][0]); acc2[5][1]=fma2(a,b0.y,acc2[5][1]);
            acc2[5][2]=fma2(a,b1.x,acc2[5][2]); acc2[5][3]=fma2(a,b1.y,acc2[5][3]);
            a = dup2f(a1.z);
            acc2[6][0]=fma2(a,b0.x,acc2[6][0]); acc2[6][1]=fma2(a,b0.y,acc2[6][1]);
            acc2[6][2]=fma2(a,b1.x,acc2[6][2]); acc2[6][3]=fma2(a,b1.y,acc2[6][3]);
            a = dup2f(a1.w);
            acc2[7][0]=fma2(a,b0.x,acc2[7][0]); acc2[7][1]=fma2(a,b0.y,acc2[7][1]);
            acc2[7][2]=fma2(a,b1.x,acc2[7][2]); acc2[7][3]=fma2(a,b1.y,acc2[7][3]);
        }
        __syncthreads();
    }
    #pragma unroll
    for (int r = 0; r < 8; r++) {
        long m = (long)bm*128 + ty*8 + r;
        #pragma unroll
        for (int cp = 0; cp < 4; cp++) {
            int n = bn*128 + tx*8 + cp*2;
            float2 v = unpack2(acc2[r][cp]);
            if (bias) { v.x += bias[n]; v.y += bias[n+1]; }
            if (do_relu) { v.x = fmaxf(v.x, 0.f); v.y = fmaxf(v.y, 0.f); }
            *(float2*)(C + m*ldc + n) = v;
        }
    }
}

// ---------------- per-row max / logsumexp (online, one pass) ----------------
__device__ __forceinline__ void ms_combine(float& m, float& s, float m2, float s2) {
    float M = fmaxf(m, m2);
    s = s * expf(m - M) + s2 * expf(m2 - M);
    m = M;
}
__global__ void k_row_reduce(const float* __restrict__ C) {
    __shared__ float sm[8], ss[8];
    int row = blockIdx.x, tid = threadIdx.x;
    const float* p = C + (long)row * VV;
    float m = -1e30f, s = 0.f;
    for (int n = tid; n < VV; n += 256) {
        float x = p[n];
        float M = fmaxf(m, x);
        s = s * expf(m - M) + expf(x - M);
        m = M;
    }
    #pragma unroll
    for (int o = 16; o; o >>= 1) {
        float m2 = __shfl_xor_sync(0xffffffffu, m, o);
        float s2 = __shfl_xor_sync(0xffffffffu, s, o);
        ms_combine(m, s, m2, s2);
    }
    int w = tid >> 5;
    if ((tid & 31) == 0) { sm[w] = m; ss[w] = s; }
    __syncthreads();
    if (tid == 0) {
        m = sm[0]; s = ss[0];
        for (int i = 1; i < 8; i++) ms_combine(m, s, sm[i], ss[i]);
        g_rowmax[row] = m;
        g_rowlse[row] = logf(s);
    }
}

// ---------------- apply log_softmax in place (float4) ----------------
__global__ void k_lsm(float* __restrict__ C) {
    long i = (long)blockIdx.x * blockDim.x + threadIdx.x;   // float4 index, exact grid
    int row = (int)(i / (VV/4));
    float sub = g_rowmax[row] + g_rowlse[row];
    float4* p = (float4*)C;
    float4 v = p[i];
    v.x -= sub; v.y -= sub; v.z -= sub; v.w -= sub;
    p[i] = v;
}

// ---------------- launch ----------------
extern "C" void kernel_launch(void* const* d_in, const int* in_sizes, int n_in,
                              void* d_out, int out_size) {
    const int*   inp     = (const int*)  d_in[0];
    const int*   tar     = (const int*)  d_in[1];
    const float* enc_emb = (const float*)d_in[2];
    const float* dec_emb = (const float*)d_in[3];
    const float* Wih_f   = (const float*)d_in[4];
    const float* Whh_f   = (const float*)d_in[5];
    const float* b_f     = (const float*)d_in[6];
    const float* Wih_b   = (const float*)d_in[7];
    const float* Whh_b   = (const float*)d_in[8];
    const float* b_b     = (const float*)d_in[9];
    const float* Wa      = (const float*)d_in[10];
    const float* va      = (const float*)d_in[11];
    const float* Wih_d   = (const float*)d_in[12];
    const float* Whh_d   = (const float*)d_in[13];
    const float* b_d     = (const float*)d_in[14];
    const float* Wout    = (const float*)d_in[15];
    const float* bout    = (const float*)d_in[16];
    float* out = (float*)d_out;

    static float *sp_enc_out = nullptr, *sp_encproj = nullptr, *sp_hs = nullptr;
    if (!sp_enc_out) {
        cudaGetSymbolAddress((void**)&sp_enc_out, g_enc_out);
        cudaGetSymbolAddress((void**)&sp_encproj, g_encproj);
        cudaGetSymbolAddress((void**)&sp_hs, g_hs);
    }

    // embeddings + state init
    k_embed<<<(2*TS*BB*EE)/256, 256>>>(inp, tar, enc_emb, dec_emb);
    k_init<<<(4*BB*HH)/256, 256>>>();

    // encoder BiLSTM, 64 steps (batched-GEMM gates + pointwise cell)
    for (int t = 0; t < TS; t++) {
        k_enc_gemm<<<dim3(8, S_ENC, 2), 256>>>(Wih_f, Whh_f, Wih_b, Whh_b, t);
        k_enc_point<<<(2*BB*HH)/256, 256>>>(b_f, b_b, t);
    }

    // decoder init + attention precompute: enc_proj = enc_out @ Wa[:, DH:]^T
    k_dec_init<<<(BB*DH)/256, 256>>>();
    sgemm_abt<<<dim3(DH/128, (TS*BB)/128), 256>>>(sp_enc_out, DH, Wa + DH, 2*DH,
                                                  nullptr, sp_encproj, DH, DH, 0);

    // decoder, 64 steps
    for (int t = 0; t < TT; t++) {
        k_hq_gemm<<<dim3(4, S_HQ), 256>>>(Wa, t);
        k_attn<<<BB, 256>>>(va);
        k_dec_gemm<<<dim3(16, S_DEC), 256>>>(Wih_d, Whh_d, t);
        k_dec_point<<<(BB*DH)/256, 256>>>(b_d, t);
    }

    // output projection + relu, then log_softmax
    sgemm_abt<<<dim3(VV/128, MOUT/128), 256>>>(sp_hs, DH, Wout, DH, bout, out, VV, DH, 1);
    k_row_reduce<<<MOUT, 256>>>(out);
    k_lsm<<<(int)(((long)MOUT*VV/4)/256), 256>>>(out);
}

// round 10
// speedup vs baseline: 1.6838x; 1.4077x over previous
#include <cuda_runtime.h>
#include <cuda_bf16.h>
#include <math.h>

// ---------------- problem constants ----------------
#define BB   32          // batch
#define TS   64          // T_src
#define TT   64          // T_tgt
#define EE   512         // embedding dim
#define HH   512         // encoder hidden (per direction)
#define DH   1024        // decoder hidden (= 2H)
#define VV   32000       // vocab
#define KD   1536        // E + 2H (decoder input concat)
#define MOUT (BB*TT)     // 2048 output rows

#define S_ENC 8          // K-splits encoder (K = 512+512 = 1024)
#define S_HQ  8          // K-splits hq      (K = 1024)
#define S_DEC 20         // K-splits decoder (K = 512+1024+1024 = 2560)

typedef unsigned long long u64;
typedef unsigned int u32;

// ---------------- device scratch (no allocs allowed) ----------------
__device__ float g_emb_src[TS*BB*EE];
__device__ float g_emb_tgt[TT*BB*EE];
__device__ float g_enc_out[TS*BB*DH];
__device__ __nv_bfloat16 g_enc_outb[TS*BB*DH];
__device__ float g_encproj[TS*BB*DH];
__device__ float g_hf[2][BB*HH];
__device__ float g_hb[2][BB*HH];
__device__ float g_cf[BB*HH];
__device__ float g_cb[BB*HH];
__device__ float g_dh[2][BB*DH];
__device__ float g_dc[BB*DH];
__device__ float g_cvec[BB*DH];
__device__ __nv_bfloat16 g_hsb[BB*TT*DH];
__device__ __nv_bfloat16 g_woutb[(long)VV*DH];
__device__ __nv_bfloat16 g_wa2b[DH*DH];
__device__ float g_rowmax[MOUT];
__device__ float g_rowlse[MOUT];
// K-split partial accumulators (gate rows are 4*H wide)
__device__ float g_pe[2][S_ENC][BB][4*HH];   // encoder gates partials (2048 cols)
__device__ float g_ph[S_HQ][BB][DH];         // hq partials            (1024 cols)
__device__ float g_pd[S_DEC][BB][4*DH];      // decoder gates partials (4096 cols)

// ---------------- helpers ----------------
__device__ __forceinline__ float warp_sum(float v) {
    #pragma unroll
    for (int o = 16; o; o >>= 1) v += __shfl_xor_sync(0xffffffffu, v, o);
    return v;
}
__device__ __forceinline__ float sigmoidf(float x) { return 1.f / (1.f + expf(-x)); }
__device__ __forceinline__ float tanh_fast(float x) {
    float y; asm("tanh.approx.f32 %0, %1;" : "=f"(y) : "f"(x)); return y;
}

// packed fp32x2 FMA (Blackwell FFMA2 — double-rate fp32)
__device__ __forceinline__ u64 fma2(u64 a, u64 b, u64 c) {
    u64 d;
    asm("fma.rn.f32x2 %0, %1, %2, %3;" : "=l"(d) : "l"(a), "l"(b), "l"(c));
    return d;
}
__device__ __forceinline__ u64 dup2f(float a) {
    u64 d;
    asm("mov.b64 %0, {%1, %1};" : "=l"(d) : "f"(a));
    return d;
}
__device__ __forceinline__ float2 unpack2(u64 v) {
    float2 r;
    asm("mov.b64 {%0, %1}, %2;" : "=f"(r.x), "=f"(r.y) : "l"(v));
    return r;
}

// bf16 tensor-core mma 16x8x16, fp32 accumulate
__device__ __forceinline__ void mma_bf16(float& c0, float& c1, float& c2, float& c3,
                                         u32 a0, u32 a1, u32 a2, u32 a3,
                                         u32 b0, u32 b1) {
    asm("mma.sync.aligned.m16n8k16.row.col.f32.bf16.bf16.f32 "
        "{%0,%1,%2,%3},{%4,%5,%6,%7},{%8,%9},{%0,%1,%2,%3};"
        : "+f"(c0), "+f"(c1), "+f"(c2), "+f"(c3)
        : "r"(a0), "r"(a1), "r"(a2), "r"(a3), "r"(b0), "r"(b1));
}

// ---------------- embedding gather (src + tgt) ----------------
__global__ void k_embed(const int* __restrict__ inp, const int* __restrict__ tar,
                        const float* __restrict__ enc_emb, const float* __restrict__ dec_emb) {
    int i = blockIdx.x * blockDim.x + threadIdx.x;     // exact grid: 2*TS*BB*EE
    const int n1 = TS * BB * EE;
    if (i < n1) {
        int t = i / (BB*EE); int r = i - t*(BB*EE); int b = r / EE; int e = r - b*EE;
        g_emb_src[i] = enc_emb[(long)inp[b*TS + t] * EE + e];
    } else {
        int j = i - n1;
        int t = j / (BB*EE); int r = j - t*(BB*EE); int b = r / EE; int e = r - b*EE;
        g_emb_tgt[j] = dec_emb[(long)tar[b*TT + t] * EE + e];
    }
}

// ---------------- zero-init encoder states ----------------
__global__ void k_init() {
    int i = blockIdx.x * blockDim.x + threadIdx.x;     // 4*BB*HH total
    const int n = BB * HH;
    if      (i <   n) g_hf[0][i]       = 0.f;
    else if (i < 2*n) g_hb[0][i - n]   = 0.f;
    else if (i < 3*n) g_cf[i - 2*n]    = 0.f;
    else              g_cb[i - 3*n]    = 0.f;
}

// ---------------- weight conversions fp32 -> bf16 ----------------
__global__ void k_cvt_wout(const float* __restrict__ W) {
    long i = (long)blockIdx.x * blockDim.x + threadIdx.x;   // per float4; exact grid
    float4 v = ((const float4*)W)[i];
    __nv_bfloat162* o = (__nv_bfloat162*)g_woutb;
    o[i*2]   = __floats2bfloat162_rn(v.x, v.y);
    o[i*2+1] = __floats2bfloat162_rn(v.z, v.w);
}
__global__ void k_cvt_wa2(const float* __restrict__ Wa) {
    int i = blockIdx.x * blockDim.x + threadIdx.x;          // per float2; DH*DH/2
    int row = i / (DH/2), col = (i % (DH/2)) * 2;
    float2 v = *(const float2*)&Wa[(long)row * (2*DH) + DH + col];
    *(__nv_bfloat162*)&g_wa2b[row*DH + col] = __floats2bfloat162_rn(v.x, v.y);
}

// =====================================================================
// gemm32 core: C_tile[32, 256] += X[32, 16k] @ W[256 cols, 16k]^T
// =====================================================================
__device__ __forceinline__ void g32_tile(const float* __restrict__ X, int xld,
                                         const float* __restrict__ W, int wld, int colbase,
                                         float Ws[16][260], float Xs[16][36],
                                         u64 acc[4][4], int tid, int tx, int ty)
{
    #pragma unroll
    for (int u = 0; u < 4; u++) {
        int idx = tid + u*256;
        int col = idx >> 2, kc = (idx & 3) * 4;
        float4 w = *(const float4*)(W + (long)(colbase + col)*wld + kc);
        Ws[kc+0][col] = w.x; Ws[kc+1][col] = w.y; Ws[kc+2][col] = w.z; Ws[kc+3][col] = w.w;
    }
    if (tid < 128) {
        int row = tid >> 2, kc = (tid & 3) * 4;
        float4 x = *(const float4*)(X + (long)row*xld + kc);
        Xs[kc+0][row] = x.x; Xs[kc+1][row] = x.y; Xs[kc+2][row] = x.z; Xs[kc+3][row] = x.w;
    }
    __syncthreads();
    #pragma unroll
    for (int kk = 0; kk < 16; kk++) {
        ulonglong2 w0 = *(const ulonglong2*)&Ws[kk][tx*8];
        ulonglong2 w1 = *(const ulonglong2*)&Ws[kk][tx*8 + 4];
        float4 xv = *(const float4*)&Xs[kk][ty*4];
        u64 a;
        a = dup2f(xv.x);
        acc[0][0] = fma2(a, w0.x, acc[0][0]); acc[0][1] = fma2(a, w0.y, acc[0][1]);
        acc[0][2] = fma2(a, w1.x, acc[0][2]); acc[0][3] = fma2(a, w1.y, acc[0][3]);
        a = dup2f(xv.y);
        acc[1][0] = fma2(a, w0.x, acc[1][0]); acc[1][1] = fma2(a, w0.y, acc[1][1]);
        acc[1][2] = fma2(a, w1.x, acc[1][2]); acc[1][3] = fma2(a, w1.y, acc[1][3]);
        a = dup2f(xv.z);
        acc[2][0] = fma2(a, w0.x, acc[2][0]); acc[2][1] = fma2(a, w0.y, acc[2][1]);
        acc[2][2] = fma2(a, w1.x, acc[2][2]); acc[2][3] = fma2(a, w1.y, acc[2][3]);
        a = dup2f(xv.w);
        acc[3][0] = fma2(a, w0.x, acc[3][0]); acc[3][1] = fma2(a, w0.y, acc[3][1]);
        acc[3][2] = fma2(a, w1.x, acc[3][2]); acc[3][3] = fma2(a, w1.y, acc[3][3]);
    }
    __syncthreads();
}

__device__ __forceinline__ void g32_store(float* out, int ldc, int colbase,
                                          u64 acc[4][4], int tx, int ty)
{
    #pragma unroll
    for (int r = 0; r < 4; r++) {
        int b = ty*4 + r;
        #pragma unroll
        for (int cp = 0; cp < 4; cp++) {
            float2 v = unpack2(acc[r][cp]);
            *(float2*)(out + (long)b*ldc + colbase + tx*8 + cp*2) = v;
        }
    }
}

// ---------------- encoder step gates: both dirs, K-split ----------------
__global__ void k_enc_gemm(const float* __restrict__ Wih_f, const float* __restrict__ Whh_f,
                           const float* __restrict__ Wih_b, const float* __restrict__ Whh_b,
                           int t) {
    __shared__ __align__(16) float Ws[16][260];
    __shared__ __align__(16) float Xs[16][36];
    int tid = threadIdx.x, tx = tid & 31, ty = tid >> 5;
    int colbase = blockIdx.x * 256;
    int sp  = blockIdx.y;
    int dir = blockIdx.z;
    int pos = dir ? (TS-1-t) : t;
    const float* Wih = dir ? Wih_b : Wih_f;
    const float* Whh = dir ? Whh_b : Whh_f;
    const float* Xe  = g_emb_src + (long)pos*BB*EE;
    const float* Xh  = dir ? g_hb[t & 1] : g_hf[t & 1];

    u64 acc[4][4];
    #pragma unroll
    for (int r = 0; r < 4; r++)
        #pragma unroll
        for (int c = 0; c < 4; c++) acc[r][c] = 0ull;

    int k0 = sp * 128;
    #pragma unroll
    for (int kt = 0; kt < 8; kt++) {
        int kg = k0 + kt*16;
        if (kg < 512) g32_tile(Xe + kg,       EE, Wih + kg,       EE, colbase, Ws, Xs, acc, tid, tx, ty);
        else          g32_tile(Xh + (kg-512), HH, Whh + (kg-512), HH, colbase, Ws, Xs, acc, tid, tx, ty);
    }
    g32_store(&g_pe[dir][sp][0][0], 4*HH, colbase, acc, tx, ty);
}

// ---------------- encoder pointwise (float2, 64-thr blocks) ----------------
__global__ void k_enc_point(const float* __restrict__ b_f, const float* __restrict__ b_b, int t) {
    int i = blockIdx.x * 64 + threadIdx.x;   // 2*BB*HH/2 = 16384 threads
    int dir = i / (BB*HH/2);
    int rem = i - dir*(BB*HH/2);
    int b = rem / (HH/2);
    int j = (rem % (HH/2)) * 2;
    const float* bias = dir ? b_b : b_f;
    float2 g0 = *(const float2*)&bias[0*HH + j];
    float2 g1 = *(const float2*)&bias[1*HH + j];
    float2 g2 = *(const float2*)&bias[2*HH + j];
    float2 g3 = *(const float2*)&bias[3*HH + j];
    #pragma unroll
    for (int s = 0; s < S_ENC; s++) {
        const float* p = &g_pe[dir][s][b][0];       // row width 4*HH
        float2 v;
        v = *(const float2*)&p[0*HH + j]; g0.x += v.x; g0.y += v.y;
        v = *(const float2*)&p[1*HH + j]; g1.x += v.x; g1.y += v.y;
        v = *(const float2*)&p[2*HH + j]; g2.x += v.x; g2.y += v.y;
        v = *(const float2*)&p[3*HH + j]; g3.x += v.x; g3.y += v.y;
    }
    float* cbuf = (dir ? g_cb : g_cf) + b*HH;
    float2 cc = *(float2*)&cbuf[j];
    float2 c, h;
    c.x = sigmoidf(g1.x) * cc.x + sigmoidf(g0.x) * tanhf(g2.x);
    c.y = sigmoidf(g1.y) * cc.y + sigmoidf(g0.y) * tanhf(g2.y);
    h.x = sigmoidf(g3.x) * tanhf(c.x);
    h.y = sigmoidf(g3.y) * tanhf(c.y);
    *(float2*)&cbuf[j] = c;
    float* hnext = (dir ? g_hb[(t+1) & 1] : g_hf[(t+1) & 1]) + b*HH;
    *(float2*)&hnext[j] = h;
    int pos = dir ? (TS-1-t) : t;
    long oidx = ((long)pos*BB + b)*DH + dir*HH + j;
    *(float2*)&g_enc_out[oidx] = h;
    *(__nv_bfloat162*)&g_enc_outb[oidx] = __floats2bfloat162_rn(h.x, h.y);
}

// ---------------- decoder init: concat encoder final states ----------------
__global__ void k_dec_init() {
    int i = blockIdx.x * blockDim.x + threadIdx.x;   // BB*DH
    int b = i / DH, o = i % DH;
    const int fin = TS & 1;                          // = 0
    float h, c;
    if (o < HH) { h = g_hf[fin][b*HH + o];      c = g_cf[b*HH + o]; }
    else        { h = g_hb[fin][b*HH + o - HH]; c = g_cb[b*HH + o - HH]; }
    g_dh[0][i] = h;
    g_dc[i]    = c;
}

// ---------------- hq = h @ Wa[:, :DH]^T, K-split ----------------
__global__ void k_hq_gemm(const float* __restrict__ Wa, int t) {
    __shared__ __align__(16) float Ws[16][260];
    __shared__ __align__(16) float Xs[16][36];
    int tid = threadIdx.x, tx = tid & 31, ty = tid >> 5;
    int colbase = blockIdx.x * 256;
    int sp = blockIdx.y;
    const float* Xh = g_dh[t & 1];

    u64 acc[4][4];
    #pragma unroll
    for (int r = 0; r < 4; r++)
        #pragma unroll
        for (int c = 0; c < 4; c++) acc[r][c] = 0ull;

    int k0 = sp * 128;  // K = 1024
    #pragma unroll
    for (int kt = 0; kt < 8; kt++) {
        int kg = k0 + kt*16;
        g32_tile(Xh + kg, DH, Wa + kg, 2*DH, colbase, Ws, Xs, acc, tid, tx, ty);
    }
    g32_store(&g_ph[sp][0][0], DH, colbase, acc, tx, ty);
}

// ---------------- decoder attention: scores, softmax, context -------------
__global__ void k_attn(const float* __restrict__ va) {
    __shared__ float s_hq[DH];
    __shared__ float s_sc[TS];
    __shared__ float s_inv;
    int b = blockIdx.x, tid = threadIdx.x;
    for (int o = tid; o < DH; o += 256) {
        float v = 0.f;
        #pragma unroll
        for (int s = 0; s < S_HQ; s++) v += g_ph[s][b][o];
        s_hq[o] = v;
    }
    __syncthreads();
    int w = tid >> 5, lane = tid & 31;
    for (int ts = w; ts < TS; ts += 8) {
        const float* ep = g_encproj + ((long)ts*BB + b)*DH;
        float s = 0.f;
        for (int o = lane; o < DH; o += 32) s += va[o] * tanh_fast(s_hq[o] + ep[o]);
        s = warp_sum(s);
        if (lane == 0) s_sc[ts] = s;
    }
    __syncthreads();
    if (tid == 0) {
        float m = -1e30f;
        for (int i = 0; i < TS; i++) m = fmaxf(m, s_sc[i]);
        float s = 0.f;
        for (int i = 0; i < TS; i++) { float e = expf(s_sc[i] - m); s_sc[i] = e; s += e; }
        s_inv = 1.f / s;
    }
    __syncthreads();
    float inv = s_inv;
    for (int o = tid; o < DH; o += 256) {
        float acc = 0.f;
        #pragma unroll 4
        for (int ts = 0; ts < TS; ts++) acc += s_sc[ts] * g_enc_out[((long)ts*BB + b)*DH + o];
        g_cvec[b*DH + o] = acc * inv;
    }
}

// ---------------- decoder gates: K-split over [emb | cvec | h] -------------
__global__ void k_dec_gemm(const float* __restrict__ Wih_d, const float* __restrict__ Whh_d,
                           int t) {
    __shared__ __align__(16) float Ws[16][260];
    __shared__ __align__(16) float Xs[16][36];
    int tid = threadIdx.x, tx = tid & 31, ty = tid >> 5;
    int colbase = blockIdx.x * 256;
    int sp = blockIdx.y;
    const float* Xe = g_emb_tgt + (long)t*BB*EE;
    const float* Xh = g_dh[t & 1];

    u64 acc[4][4];
    #pragma unroll
    for (int r = 0; r < 4; r++)
        #pragma unroll
        for (int c = 0; c < 4; c++) acc[r][c] = 0ull;

    int k0 = sp * 128;   // K = 2560
    #pragma unroll
    for (int kt = 0; kt < 8; kt++) {
        int kg = k0 + kt*16;
        if      (kg < 512)  g32_tile(Xe + kg,           EE, Wih_d + kg,        KD, colbase, Ws, Xs, acc, tid, tx, ty);
        else if (kg < 1536) g32_tile(g_cvec + (kg-512), DH, Wih_d + kg,        KD, colbase, Ws, Xs, acc, tid, tx, ty);
        else                g32_tile(Xh + (kg-1536),    DH, Whh_d + (kg-1536), DH, colbase, Ws, Xs, acc, tid, tx, ty);
    }
    g32_store(&g_pd[sp][0][0], 4*DH, colbase, acc, tx, ty);
}

// ---------------- decoder pointwise (float2, 64-thr blocks) ----------------
__global__ void k_dec_point(const float* __restrict__ b_d, int t) {
    int i = blockIdx.x * 64 + threadIdx.x;   // BB*DH/2 = 16384 threads
    int b = i / (DH/2);
    int j = (i % (DH/2)) * 2;
    float2 g0 = *(const float2*)&b_d[0*DH + j];
    float2 g1 = *(const float2*)&b_d[1*DH + j];
    float2 g2 = *(const float2*)&b_d[2*DH + j];
    float2 g3 = *(const float2*)&b_d[3*DH + j];
    #pragma unroll
    for (int s = 0; s < S_DEC; s++) {
        const float* p = &g_pd[s][b][0];
        float2 v;
        v = *(const float2*)&p[0*DH + j]; g0.x += v.x; g0.y += v.y;
        v = *(const float2*)&p[1*DH + j]; g1.x += v.x; g1.y += v.y;
        v = *(const float2*)&p[2*DH + j]; g2.x += v.x; g2.y += v.y;
        v = *(const float2*)&p[3*DH + j]; g3.x += v.x; g3.y += v.y;
    }
    long si = (long)b*DH + j;
    float2 cc = *(float2*)&g_dc[si];
    float2 c, h;
    c.x = sigmoidf(g1.x) * cc.x + sigmoidf(g0.x) * tanhf(g2.x);
    c.y = sigmoidf(g1.y) * cc.y + sigmoidf(g0.y) * tanhf(g2.y);
    h.x = sigmoidf(g3.x) * tanhf(c.x);
    h.y = sigmoidf(g3.y) * tanhf(c.y);
    *(float2*)&g_dc[si] = c;
    *(float2*)&g_dh[(t+1) & 1][si] = h;
    *(__nv_bfloat162*)&g_hsb[((long)b*TT + t)*DH + j] = __floats2bfloat162_rn(h.x, h.y);
}

// =====================================================================
// bf16 tensor-core GEMM: C[M,N] = A[M,K] @ B[N,K]^T (+bias, +relu)
// 128x128 block tile, BK=32, 256 threads = 8 warps (2m x 4n), warp 64x32.
// mma.m16n8k16 bf16 -> fp32. M,N % 128 == 0, K % 32 == 0.
// =====================================================================
__global__ void hgemm_abt(const __nv_bfloat16* __restrict__ A, int lda,
                          const __nv_bfloat16* __restrict__ B, int ldb,
                          const float* __restrict__ bias,
                          float* __restrict__ C, int ldc,
                          int K, int do_relu) {
    __shared__ __align__(16) __nv_bfloat16 As[128*40];   // stride 40 (pad 8)
    __shared__ __align__(16) __nv_bfloat16 Bs[128*40];
    int tid = threadIdx.x;
    int bm = blockIdx.y, bn = blockIdx.x;
    int warp = tid >> 5, lane = tid & 31;
    int wm = warp & 1, wn = warp >> 1;        // 2 x 4 warp grid
    int grp = lane >> 2, tg = lane & 3;

    const __nv_bfloat16* Ag = A + (long)bm*128*lda;
    const __nv_bfloat16* Bg = B + (long)bn*128*ldb;
    uint4* As4 = (uint4*)As;
    uint4* Bs4 = (uint4*)Bs;

    float acc[4][4][4];
    #pragma unroll
    for (int mt = 0; mt < 4; mt++)
        #pragma unroll
        for (int nt = 0; nt < 4; nt++)
            #pragma unroll
            for (int q = 0; q < 4; q++) acc[mt][nt][q] = 0.f;

    for (int k0 = 0; k0 < K; k0 += 32) {
        #pragma unroll
        for (int u = 0; u < 2; u++) {
            int idx = tid + u*256;
            int row = idx >> 2, c8 = (idx & 3) * 8;
            As4[row*5 + (c8 >> 3)] = *(const uint4*)(Ag + (long)row*lda + k0 + c8);
            Bs4[row*5 + (c8 >> 3)] = *(const uint4*)(Bg + (long)row*ldb + k0 + c8);
        }
        __syncthreads();
        #pragma unroll
        for (int ks = 0; ks < 2; ks++) {
            int kof = ks*16 + tg*2;
            u32 af[4][4], bf[4][2];
            #pragma unroll
            for (int mt = 0; mt < 4; mt++) {
                int m0 = wm*64 + mt*16 + grp;
                af[mt][0] = *(const u32*)&As[(m0    )*40 + kof    ];
                af[mt][1] = *(const u32*)&As[(m0 + 8)*40 + kof    ];
                af[mt][2] = *(const u32*)&As[(m0    )*40 + kof + 8];
                af[mt][3] = *(const u32*)&As[(m0 + 8)*40 + kof + 8];
            }
            #pragma unroll
            for (int nt = 0; nt < 4; nt++) {
                int n0 = wn*32 + nt*8 + grp;
                bf[nt][0] = *(const u32*)&Bs[n0*40 + kof    ];
                bf[nt][1] = *(const u32*)&Bs[n0*40 + kof + 8];
            }
            #pragma unroll
            for (int mt = 0; mt < 4; mt++)
                #pragma unroll
                for (int nt = 0; nt < 4; nt++)
                    mma_bf16(acc[mt][nt][0], acc[mt][nt][1], acc[mt][nt][2], acc[mt][nt][3],
                             af[mt][0], af[mt][1], af[mt][2], af[mt][3],
                             bf[nt][0], bf[nt][1]);
        }
        __syncthreads();
    }

    #pragma unroll
    for (int mt = 0; mt < 4; mt++) {
        long m = (long)bm*128 + wm*64 + mt*16 + grp;
        #pragma unroll
        for (int nt = 0; nt < 4; nt++) {
            int n = bn*128 + wn*32 + nt*8 + tg*2;
            float2 v0 = make_float2(acc[mt][nt][0], acc[mt][nt][1]);
            float2 v1 = make_float2(acc[mt][nt][2], acc[mt][nt][3]);
            if (bias) {
                float2 bb = *(const float2*)&bias[n];
                v0.x += bb.x; v0.y += bb.y; v1.x += bb.x; v1.y += bb.y;
            }
            if (do_relu) {
                v0.x = fmaxf(v0.x, 0.f); v0.y = fmaxf(v0.y, 0.f);
                v1.x = fmaxf(v1.x, 0.f); v1.y = fmaxf(v1.y, 0.f);
            }
            *(float2*)&C[m*ldc + n]     = v0;
            *(float2*)&C[(m+8)*ldc + n] = v1;
        }
    }
}

// ---------------- per-row max / logsumexp (online, one pass) ----------------
__device__ __forceinline__ void ms_combine(float& m, float& s, float m2, float s2) {
    float M = fmaxf(m, m2);
    s = s * expf(m - M) + s2 * expf(m2 - M);
    m = M;
}
__global__ void k_row_reduce(const float* __restrict__ C) {
    __shared__ float sm[8], ss[8];
    int row = blockIdx.x, tid = threadIdx.x;
    const float* p = C + (long)row * VV;
    float m = -1e30f, s = 0.f;
    for (int n = tid; n < VV; n += 256) {
        float x = p[n];
        float M = fmaxf(m, x);
        s = s * expf(m - M) + expf(x - M);
        m = M;
    }
    #pragma unroll
    for (int o = 16; o; o >>= 1) {
        float m2 = __shfl_xor_sync(0xffffffffu, m, o);
        float s2 = __shfl_xor_sync(0xffffffffu, s, o);
        ms_combine(m, s, m2, s2);
    }
    int w = tid >> 5;
    if ((tid & 31) == 0) { sm[w] = m; ss[w] = s; }
    __syncthreads();
    if (tid == 0) {
        m = sm[0]; s = ss[0];
        for (int i = 1; i < 8; i++) ms_combine(m, s, sm[i], ss[i]);
        g_rowmax[row] = m;
        g_rowlse[row] = logf(s);
    }
}

// ---------------- apply log_softmax in place (float4) ----------------
__global__ void k_lsm(float* __restrict__ C) {
    long i = (long)blockIdx.x * blockDim.x + threadIdx.x;   // float4 index, exact grid
    int row = (int)(i / (VV/4));
    float sub = g_rowmax[row] + g_rowlse[row];
    float4* p = (float4*)C;
    float4 v = p[i];
    v.x -= sub; v.y -= sub; v.z -= sub; v.w -= sub;
    p[i] = v;
}

// ---------------- launch ----------------
extern "C" void kernel_launch(void* const* d_in, const int* in_sizes, int n_in,
                              void* d_out, int out_size) {
    const int*   inp     = (const int*)  d_in[0];
    const int*   tar     = (const int*)  d_in[1];
    const float* enc_emb = (const float*)d_in[2];
    const float* dec_emb = (const float*)d_in[3];
    const float* Wih_f   = (const float*)d_in[4];
    const float* Whh_f   = (const float*)d_in[5];
    const float* b_f     = (const float*)d_in[6];
    const float* Wih_b   = (const float*)d_in[7];
    const float* Whh_b   = (const float*)d_in[8];
    const float* b_b     = (const float*)d_in[9];
    const float* Wa      = (const float*)d_in[10];
    const float* va      = (const float*)d_in[11];
    const float* Wih_d   = (const float*)d_in[12];
    const float* Whh_d   = (const float*)d_in[13];
    const float* b_d     = (const float*)d_in[14];
    const float* Wout    = (const float*)d_in[15];
    const float* bout    = (const float*)d_in[16];
    float* out = (float*)d_out;

    static float *sp_encproj = nullptr;
    static __nv_bfloat16 *sp_enc_outb = nullptr, *sp_hsb = nullptr, *sp_woutb = nullptr, *sp_wa2b = nullptr;
    if (!sp_encproj) {
        cudaGetSymbolAddress((void**)&sp_encproj, g_encproj);
        cudaGetSymbolAddress((void**)&sp_enc_outb, g_enc_outb);
        cudaGetSymbolAddress((void**)&sp_hsb, g_hsb);
        cudaGetSymbolAddress((void**)&sp_woutb, g_woutb);
        cudaGetSymbolAddress((void**)&sp_wa2b, g_wa2b);
    }

    // embeddings + state init + weight conversions
    k_embed<<<(2*TS*BB*EE)/256, 256>>>(inp, tar, enc_emb, dec_emb);
    k_init<<<(4*BB*HH)/256, 256>>>();
    k_cvt_wout<<<(int)(((long)VV*DH/4)/256), 256>>>(Wout);
    k_cvt_wa2<<<(DH*DH/2)/256, 256>>>(Wa);

    // encoder BiLSTM, 64 steps
    for (int t = 0; t < TS; t++) {
        k_enc_gemm<<<dim3(8, S_ENC, 2), 256>>>(Wih_f, Whh_f, Wih_b, Whh_b, t);
        k_enc_point<<<(2*BB*HH/2)/64, 64>>>(b_f, b_b, t);
    }

    // decoder init + attention precompute: enc_proj = enc_out @ Wa[:, DH:]^T (bf16 MMA)
    k_dec_init<<<(BB*DH)/256, 256>>>();
    hgemm_abt<<<dim3(DH/128, (TS*BB)/128), 256>>>(sp_enc_outb, DH, sp_wa2b, DH,
                                                  nullptr, sp_encproj, DH, DH, 0);

    // decoder, 64 steps
    for (int t = 0; t < TT; t++) {
        k_hq_gemm<<<dim3(4, S_HQ), 256>>>(Wa, t);
        k_attn<<<BB, 256>>>(va);
        k_dec_gemm<<<dim3(16, S_DEC), 256>>>(Wih_d, Whh_d, t);
        k_dec_point<<<(BB*DH/2)/64, 64>>>(b_d, t);
    }

    // output projection + relu (bf16 MMA), then log_softmax
    hgemm_abt<<<dim3(VV/128, MOUT/128), 256>>>(sp_hsb, DH, sp_woutb, DH,
                                               bout, out, VV, DH, 1);
    k_row_reduce<<<MOUT, 256>>>(out);
    k_lsm<<<(int)(((long)MOUT*VV/4)/256), 256>>>(out);
}

// round 11
// speedup vs baseline: 3.3019x; 1.9609x over previous
#include <cuda_runtime.h>
#include <cuda_bf16.h>
#include <math.h>

// ---------------- problem constants ----------------
#define BB   32          // batch
#define TS   64          // T_src
#define TT   64          // T_tgt
#define EE   512         // embedding dim
#define HH   512         // encoder hidden (per direction)
#define DH   1024        // decoder hidden (= 2H)
#define VV   32000       // vocab
#define MOUT (BB*TT)     // 2048 output rows
#define ND1  (4*DH + DH) // merged decoder gemm1 width: 4096 gates + 1024 hq = 5120

typedef unsigned long long u64;
typedef unsigned int u32;
typedef __nv_bfloat16 bf16;

// ---------------- device scratch (no allocs allowed) ----------------
__device__ bf16  g_emb_srcb[TS*BB*EE];
__device__ bf16  g_emb_tgtb[TT*BB*EE];
__device__ float g_enc_out [TS*BB*DH];
__device__ bf16  g_enc_outb[TS*BB*DH];
__device__ float g_encproj [TS*BB*DH];
// bf16 weights (converted once)
__device__ bf16 g_wihfb[4*HH*EE];
__device__ bf16 g_whhfb[4*HH*HH];
__device__ bf16 g_wihbb[4*HH*EE];
__device__ bf16 g_whhbb[4*HH*HH];
__device__ bf16 g_wih1db[(long)4*DH*EE];   // Wih_d[:, 0:512]
__device__ bf16 g_wih2db[(long)4*DH*DH];   // Wih_d[:, 512:1536]
__device__ bf16 g_whhdb[(long)4*DH*DH];
__device__ bf16 g_wa1b[DH*DH];             // Wa[:, 0:DH]
__device__ bf16 g_wa2b[DH*DH];             // Wa[:, DH:2DH]
__device__ bf16 g_woutb[(long)VV*DH];
// precomputed input-side gate contributions (fp32)
__device__ float g_gxe[2][TS*BB][4*HH];    // encoder emb@Wih^T per dir
__device__ float g_gxd[TT*BB][4*DH];       // decoder emb@Wih1^T
// recurrent states
__device__ bf16  g_hfb[2][BB*HH];
__device__ bf16  g_hbb[2][BB*HH];
__device__ float g_cf[BB*HH];
__device__ float g_cb[BB*HH];
__device__ bf16  g_dhb[2][BB*DH];
__device__ float g_dc[BB*DH];
__device__ bf16  g_cvecb[BB*DH];
__device__ bf16  g_hsb[BB*TT*DH];
__device__ float g_rowmax[MOUT];
__device__ float g_rowlse[MOUT];
// K-split partial accumulators (fp32)
__device__ float g_pe[2][2][BB][4*HH];     // encoder: dir x 2 k-splits
__device__ float g_pd1[4][BB][ND1];        // decoder h-gemm (gates + hq), 4 k-splits
__device__ float g_pd2[4][BB][4*DH];       // decoder cvec-gemm, 4 k-splits

// ---------------- helpers ----------------
__device__ __forceinline__ float warp_sum(float v) {
    #pragma unroll
    for (int o = 16; o; o >>= 1) v += __shfl_xor_sync(0xffffffffu, v, o);
    return v;
}
__device__ __forceinline__ float sigmoidf(float x) { return 1.f / (1.f + expf(-x)); }
__device__ __forceinline__ float tanh_fast(float x) {
    float y; asm("tanh.approx.f32 %0, %1;" : "=f"(y) : "f"(x)); return y;
}
__device__ __forceinline__ void mma_bf16(float& c0, float& c1, float& c2, float& c3,
                                         u32 a0, u32 a1, u32 a2, u32 a3,
                                         u32 b0, u32 b1) {
    asm("mma.sync.aligned.m16n8k16.row.col.f32.bf16.bf16.f32 "
        "{%0,%1,%2,%3},{%4,%5,%6,%7},{%8,%9},{%0,%1,%2,%3};"
        : "+f"(c0), "+f"(c1), "+f"(c2), "+f"(c3)
        : "r"(a0), "r"(a1), "r"(a2), "r"(a3), "r"(b0), "r"(b1));
}

// ---------------- embedding gather (src + tgt) -> bf16 ----------------
__global__ void k_embed(const int* __restrict__ inp, const int* __restrict__ tar,
                        const float* __restrict__ enc_emb, const float* __restrict__ dec_emb) {
    int i = blockIdx.x * blockDim.x + threadIdx.x;     // exact grid: 2*TS*BB*EE
    const int n1 = TS * BB * EE;
    if (i < n1) {
        int t = i / (BB*EE); int r = i - t*(BB*EE); int b = r / EE; int e = r - b*EE;
        g_emb_srcb[i] = __float2bfloat16(enc_emb[(long)inp[b*TS + t] * EE + e]);
    } else {
        int j = i - n1;
        int t = j / (BB*EE); int r = j - t*(BB*EE); int b = r / EE; int e = r - b*EE;
        g_emb_tgtb[j] = __float2bfloat16(dec_emb[(long)tar[b*TT + t] * EE + e]);
    }
}

// ---------------- zero-init encoder states ----------------
__global__ void k_init() {
    int i = blockIdx.x * blockDim.x + threadIdx.x;     // BB*HH threads
    g_hfb[0][i] = __float2bfloat16(0.f);
    g_hbb[0][i] = __float2bfloat16(0.f);
    g_cf[i] = 0.f;
    g_cb[i] = 0.f;
}

// ---------------- conversions fp32 -> bf16 ----------------
__global__ void k_cvt_contig(const float* __restrict__ src, bf16* __restrict__ dst) {
    long i = (long)blockIdx.x * blockDim.x + threadIdx.x;    // per float4, exact grid
    float4 v = ((const float4*)src)[i];
    __nv_bfloat162* o = (__nv_bfloat162*)dst;
    o[i*2]   = __floats2bfloat162_rn(v.x, v.y);
    o[i*2+1] = __floats2bfloat162_rn(v.z, v.w);
}
__global__ void k_cvt_strided(const float* __restrict__ src, bf16* __restrict__ dst,
                              int srcld, int coloff, int outw) {
    long i = (long)blockIdx.x * blockDim.x + threadIdx.x;    // per float2, exact grid
    int row = (int)(i / (outw/2));
    int col = (int)(i % (outw/2)) * 2;
    float2 v = *(const float2*)&src[(long)row*srcld + coloff + col];
    *(__nv_bfloat162*)&dst[(long)row*outw + col] = __floats2bfloat162_rn(v.x, v.y);
}

// =====================================================================
// skinny bf16 GEMM core: out[32, 128] (fp32) = X[32, kslice] @ W[128, kslice]^T
// 256 threads = 8 warps (2m x 4n); BK=32, smem stride 40 bf16.
// =====================================================================
__device__ __forceinline__ void hg32_core(
    const bf16* __restrict__ X, int xld,
    const bf16* __restrict__ W, int wld,
    int kslice, float* __restrict__ out, int ldc,
    bf16* Xs, bf16* Ws)
{
    int tid = threadIdx.x;
    int warp = tid >> 5, lane = tid & 31;
    int wm = warp & 1, wn = warp >> 1;
    int grp = lane >> 2, tg = lane & 3;
    uint4* Xs4 = (uint4*)Xs;
    uint4* Ws4 = (uint4*)Ws;

    float acc[4][4];
    #pragma unroll
    for (int nt = 0; nt < 4; nt++)
        #pragma unroll
        for (int q = 0; q < 4; q++) acc[nt][q] = 0.f;

    for (int k0 = 0; k0 < kslice; k0 += 32) {
        #pragma unroll
        for (int u = 0; u < 2; u++) {
            int idx = tid + u*256;
            int row = idx >> 2, c8 = (idx & 3) * 8;
            Ws4[row*5 + (c8 >> 3)] = *(const uint4*)(W + (long)row*wld + k0 + c8);
        }
        if (tid < 128) {
            int row = tid >> 2, c8 = (tid & 3) * 8;
            Xs4[row*5 + (c8 >> 3)] = *(const uint4*)(X + (long)row*xld + k0 + c8);
        }
        __syncthreads();
        #pragma unroll
        for (int ks = 0; ks < 2; ks++) {
            int kof = ks*16 + tg*2;
            int m0 = wm*16 + grp;
            u32 a0 = *(const u32*)&Xs[m0*40 + kof];
            u32 a1 = *(const u32*)&Xs[(m0+8)*40 + kof];
            u32 a2 = *(const u32*)&Xs[m0*40 + kof + 8];
            u32 a3 = *(const u32*)&Xs[(m0+8)*40 + kof + 8];
            #pragma unroll
            for (int nt = 0; nt < 4; nt++) {
                int n0 = wn*32 + nt*8 + grp;
                u32 b0 = *(const u32*)&Ws[n0*40 + kof];
                u32 b1 = *(const u32*)&Ws[n0*40 + kof + 8];
                mma_bf16(acc[nt][0], acc[nt][1], acc[nt][2], acc[nt][3],
                         a0, a1, a2, a3, b0, b1);
            }
        }
        __syncthreads();
    }
    int m0 = wm*16 + grp;
    #pragma unroll
    for (int nt = 0; nt < 4; nt++) {
        int n = wn*32 + nt*8 + tg*2;
        *(float2*)&out[(long)m0*ldc + n]     = make_float2(acc[nt][0], acc[nt][1]);
        *(float2*)&out[(long)(m0+8)*ldc + n] = make_float2(acc[nt][2], acc[nt][3]);
    }
}

// ---------------- encoder recurrent gemm: gates_h = h @ Whh^T ----------------
// grid (16, 2, 2): x = 128-col tile of 2048, y = k-split (K=512 -> 2x256), z = dir
__global__ void k_enc_hgemm(int t) {
    __shared__ __align__(16) bf16 Xs[32*40];
    __shared__ __align__(16) bf16 Ws[128*40];
    int c0 = blockIdx.x * 128, sp = blockIdx.y, dir = blockIdx.z;
    int k0 = sp * 256;
    const bf16* X = (dir ? g_hbb[t & 1] : g_hfb[t & 1]) + k0;
    const bf16* W = (dir ? g_whhbb : g_whhfb) + (long)c0*HH + k0;
    float* out = &g_pe[dir][sp][0][0] + c0;
    hg32_core(X, HH, W, HH, 256, out, 4*HH, Xs, Ws);
}

// ---------------- encoder pointwise ----------------
__global__ void k_enc_point(const float* __restrict__ b_f, const float* __restrict__ b_b, int t) {
    int i = blockIdx.x * 64 + threadIdx.x;   // 2*BB*HH/2 threads
    int dir = i / (BB*HH/2);
    int rem = i - dir*(BB*HH/2);
    int b = rem / (HH/2);
    int j = (rem % (HH/2)) * 2;
    int pos = dir ? (TS-1-t) : t;
    const float* bias = dir ? b_b : b_f;
    const float* gx = &g_gxe[dir][pos*BB + b][0];
    float2 g0 = *(const float2*)&bias[0*HH + j];
    float2 g1 = *(const float2*)&bias[1*HH + j];
    float2 g2 = *(const float2*)&bias[2*HH + j];
    float2 g3 = *(const float2*)&bias[3*HH + j];
    float2 v;
    v = *(const float2*)&gx[0*HH + j]; g0.x += v.x; g0.y += v.y;
    v = *(const float2*)&gx[1*HH + j]; g1.x += v.x; g1.y += v.y;
    v = *(const float2*)&gx[2*HH + j]; g2.x += v.x; g2.y += v.y;
    v = *(const float2*)&gx[3*HH + j]; g3.x += v.x; g3.y += v.y;
    #pragma unroll
    for (int s = 0; s < 2; s++) {
        const float* p = &g_pe[dir][s][b][0];
        v = *(const float2*)&p[0*HH + j]; g0.x += v.x; g0.y += v.y;
        v = *(const float2*)&p[1*HH + j]; g1.x += v.x; g1.y += v.y;
        v = *(const float2*)&p[2*HH + j]; g2.x += v.x; g2.y += v.y;
        v = *(const float2*)&p[3*HH + j]; g3.x += v.x; g3.y += v.y;
    }
    float* cbuf = (dir ? g_cb : g_cf) + b*HH;
    float2 cc = *(float2*)&cbuf[j];
    float2 c, h;
    c.x = sigmoidf(g1.x) * cc.x + sigmoidf(g0.x) * tanhf(g2.x);
    c.y = sigmoidf(g1.y) * cc.y + sigmoidf(g0.y) * tanhf(g2.y);
    h.x = sigmoidf(g3.x) * tanhf(c.x);
    h.y = sigmoidf(g3.y) * tanhf(c.y);
    *(float2*)&cbuf[j] = c;
    bf16* hnext = (dir ? g_hbb[(t+1) & 1] : g_hfb[(t+1) & 1]) + b*HH;
    *(__nv_bfloat162*)&hnext[j] = __floats2bfloat162_rn(h.x, h.y);
    long oidx = ((long)pos*BB + b)*DH + dir*HH + j;
    *(float2*)&g_enc_out[oidx] = h;
    *(__nv_bfloat162*)&g_enc_outb[oidx] = __floats2bfloat162_rn(h.x, h.y);
}

// ---------------- decoder init: concat encoder final states ----------------
__global__ void k_dec_init() {
    int i = blockIdx.x * blockDim.x + threadIdx.x;   // BB*DH
    int b = i / DH, o = i % DH;
    bf16 h; float c;
    if (o < HH) { h = g_hfb[0][b*HH + o];      c = g_cf[b*HH + o]; }
    else        { h = g_hbb[0][b*HH + o - HH]; c = g_cb[b*HH + o - HH]; }
    g_dhb[0][i] = h;
    g_dc[i]     = c;
}

// ---------------- decoder gemm1: [gates_h | hq] = h @ [Whh_d | Wa1]^T -------
// grid (40, 4): x = 128-col tile of 5120, y = k-split (K=1024 -> 4x256)
__global__ void k_dec_hgemm1(int t) {
    __shared__ __align__(16) bf16 Xs[32*40];
    __shared__ __align__(16) bf16 Ws[128*40];
    int c0 = blockIdx.x * 128, sp = blockIdx.y;
    int k0 = sp * 256;
    const bf16* X = g_dhb[t & 1] + k0;
    const bf16* W = (c0 < 4*DH) ? (g_whhdb + (long)c0*DH + k0)
                                : (g_wa1b + (long)(c0 - 4*DH)*DH + k0);
    float* out = &g_pd1[sp][0][0] + c0;
    hg32_core(X, DH, W, DH, 256, out, ND1, Xs, Ws);
}

// ---------------- decoder attention: scores, softmax, context -------------
__global__ void k_attn(const float* __restrict__ va) {
    __shared__ float s_hq[DH];
    __shared__ float s_sc[TS];
    __shared__ float s_inv;
    int b = blockIdx.x, tid = threadIdx.x;
    for (int o = tid; o < DH; o += 256) {
        float v = 0.f;
        #pragma unroll
        for (int s = 0; s < 4; s++) v += g_pd1[s][b][4*DH + o];
        s_hq[o] = v;
    }
    __syncthreads();
    int w = tid >> 5, lane = tid & 31;
    for (int ts = w; ts < TS; ts += 8) {
        const float* ep = g_encproj + ((long)ts*BB + b)*DH;
        float s = 0.f;
        for (int o = lane; o < DH; o += 32) s += va[o] * tanh_fast(s_hq[o] + ep[o]);
        s = warp_sum(s);
        if (lane == 0) s_sc[ts] = s;
    }
    __syncthreads();
    if (tid == 0) {
        float m = -1e30f;
        for (int i = 0; i < TS; i++) m = fmaxf(m, s_sc[i]);
        float s = 0.f;
        for (int i = 0; i < TS; i++) { float e = expf(s_sc[i] - m); s_sc[i] = e; s += e; }
        s_inv = 1.f / s;
    }
    __syncthreads();
    float inv = s_inv;
    for (int o = tid; o < DH; o += 256) {
        float acc = 0.f;
        #pragma unroll 4
        for (int ts = 0; ts < TS; ts++) acc += s_sc[ts] * g_enc_out[((long)ts*BB + b)*DH + o];
        g_cvecb[b*DH + o] = __float2bfloat16(acc * inv);
    }
}

// ---------------- decoder gemm2: gates_c = cvec @ Wih2^T ----------------
// grid (32, 4): K=1024 -> 4x256
__global__ void k_dec_hgemm2() {
    __shared__ __align__(16) bf16 Xs[32*40];
    __shared__ __align__(16) bf16 Ws[128*40];
    int c0 = blockIdx.x * 128, sp = blockIdx.y;
    int k0 = sp * 256;
    const bf16* X = g_cvecb + k0;
    const bf16* W = g_wih2db + (long)c0*DH + k0;
    float* out = &g_pd2[sp][0][0] + c0;
    hg32_core(X, DH, W, DH, 256, out, 4*DH, Xs, Ws);
}

// ---------------- decoder pointwise ----------------
__global__ void k_dec_point(const float* __restrict__ b_d, int t) {
    int i = blockIdx.x * 64 + threadIdx.x;   // BB*DH/2 threads
    int b = i / (DH/2);
    int j = (i % (DH/2)) * 2;
    const float* gx = &g_gxd[t*BB + b][0];
    float2 g0 = *(const float2*)&b_d[0*DH + j];
    float2 g1 = *(const float2*)&b_d[1*DH + j];
    float2 g2 = *(const float2*)&b_d[2*DH + j];
    float2 g3 = *(const float2*)&b_d[3*DH + j];
    float2 v;
    v = *(const float2*)&gx[0*DH + j]; g0.x += v.x; g0.y += v.y;
    v = *(const float2*)&gx[1*DH + j]; g1.x += v.x; g1.y += v.y;
    v = *(const float2*)&gx[2*DH + j]; g2.x += v.x; g2.y += v.y;
    v = *(const float2*)&gx[3*DH + j]; g3.x += v.x; g3.y += v.y;
    #pragma unroll
    for (int s = 0; s < 4; s++) {
        const float* p1 = &g_pd1[s][b][0];
        const float* p2 = &g_pd2[s][b][0];
        v = *(const float2*)&p1[0*DH + j]; g0.x += v.x; g0.y += v.y;
        v = *(const float2*)&p1[1*DH + j]; g1.x += v.x; g1.y += v.y;
        v = *(const float2*)&p1[2*DH + j]; g2.x += v.x; g2.y += v.y;
        v = *(const float2*)&p1[3*DH + j]; g3.x += v.x; g3.y += v.y;
        v = *(const float2*)&p2[0*DH + j]; g0.x += v.x; g0.y += v.y;
        v = *(const float2*)&p2[1*DH + j]; g1.x += v.x; g1.y += v.y;
        v = *(const float2*)&p2[2*DH + j]; g2.x += v.x; g2.y += v.y;
        v = *(const float2*)&p2[3*DH + j]; g3.x += v.x; g3.y += v.y;
    }
    long si = (long)b*DH + j;
    float2 cc = *(float2*)&g_dc[si];
    float2 c, h;
    c.x = sigmoidf(g1.x) * cc.x + sigmoidf(g0.x) * tanhf(g2.x);
    c.y = sigmoidf(g1.y) * cc.y + sigmoidf(g0.y) * tanhf(g2.y);
    h.x = sigmoidf(g3.x) * tanhf(c.x);
    h.y = sigmoidf(g3.y) * tanhf(c.y);
    *(float2*)&g_dc[si] = c;
    *(__nv_bfloat162*)&g_dhb[(t+1) & 1][si] = __floats2bfloat162_rn(h.x, h.y);
    *(__nv_bfloat162*)&g_hsb[((long)b*TT + t)*DH + j] = __floats2bfloat162_rn(h.x, h.y);
}

// =====================================================================
// bf16 tensor-core GEMM: C[M,N] = A[M,K] @ B[N,K]^T (+bias, +relu), fp32 C
// 128x128 block tile, BK=32, 256 threads; validated in R10.
// =====================================================================
__global__ void hgemm_abt(const bf16* __restrict__ A, int lda,
                          const bf16* __restrict__ B, int ldb,
                          const float* __restrict__ bias,
                          float* __restrict__ C, int ldc,
                          int K, int do_relu) {
    __shared__ __align__(16) bf16 As[128*40];
    __shared__ __align__(16) bf16 Bs[128*40];
    int tid = threadIdx.x;
    int bm = blockIdx.y, bn = blockIdx.x;
    int warp = tid >> 5, lane = tid & 31;
    int wm = warp & 1, wn = warp >> 1;
    int grp = lane >> 2, tg = lane & 3;

    const bf16* Ag = A + (long)bm*128*lda;
    const bf16* Bg = B + (long)bn*128*ldb;
    uint4* As4 = (uint4*)As;
    uint4* Bs4 = (uint4*)Bs;

    float acc[4][4][4];
    #pragma unroll
    for (int mt = 0; mt < 4; mt++)
        #pragma unroll
        for (int nt = 0; nt < 4; nt++)
            #pragma unroll
            for (int q = 0; q < 4; q++) acc[mt][nt][q] = 0.f;

    for (int k0 = 0; k0 < K; k0 += 32) {
        #pragma unroll
        for (int u = 0; u < 2; u++) {
            int idx = tid + u*256;
            int row = idx >> 2, c8 = (idx & 3) * 8;
            As4[row*5 + (c8 >> 3)] = *(const uint4*)(Ag + (long)row*lda + k0 + c8);
            Bs4[row*5 + (c8 >> 3)] = *(const uint4*)(Bg + (long)row*ldb + k0 + c8);
        }
        __syncthreads();
        #pragma unroll
        for (int ks = 0; ks < 2; ks++) {
            int kof = ks*16 + tg*2;
            u32 af[4][4], bf[4][2];
            #pragma unroll
            for (int mt = 0; mt < 4; mt++) {
                int m0 = wm*64 + mt*16 + grp;
                af[mt][0] = *(const u32*)&As[(m0    )*40 + kof    ];
                af[mt][1] = *(const u32*)&As[(m0 + 8)*40 + kof    ];
                af[mt][2] = *(const u32*)&As[(m0    )*40 + kof + 8];
                af[mt][3] = *(const u32*)&As[(m0 + 8)*40 + kof + 8];
            }
            #pragma unroll
            for (int nt = 0; nt < 4; nt++) {
                int n0 = wn*32 + nt*8 + grp;
                bf[nt][0] = *(const u32*)&Bs[n0*40 + kof    ];
                bf[nt][1] = *(const u32*)&Bs[n0*40 + kof + 8];
            }
            #pragma unroll
            for (int mt = 0; mt < 4; mt++)
                #pragma unroll
                for (int nt = 0; nt < 4; nt++)
                    mma_bf16(acc[mt][nt][0], acc[mt][nt][1], acc[mt][nt][2], acc[mt][nt][3],
                             af[mt][0], af[mt][1], af[mt][2], af[mt][3],
                             bf[nt][0], bf[nt][1]);
        }
        __syncthreads();
    }

    #pragma unroll
    for (int mt = 0; mt < 4; mt++) {
        long m = (long)bm*128 + wm*64 + mt*16 + grp;
        #pragma unroll
        for (int nt = 0; nt < 4; nt++) {
            int n = bn*128 + wn*32 + nt*8 + tg*2;
            float2 v0 = make_float2(acc[mt][nt][0], acc[mt][nt][1]);
            float2 v1 = make_float2(acc[mt][nt][2], acc[mt][nt][3]);
            if (bias) {
                float2 bb = *(const float2*)&bias[n];
                v0.x += bb.x; v0.y += bb.y; v1.x += bb.x; v1.y += bb.y;
            }
            if (do_relu) {
                v0.x = fmaxf(v0.x, 0.f); v0.y = fmaxf(v0.y, 0.f);
                v1.x = fmaxf(v1.x, 0.f); v1.y = fmaxf(v1.y, 0.f);
            }
            *(float2*)&C[m*ldc + n]     = v0;
            *(float2*)&C[(m+8)*ldc + n] = v1;
        }
    }
}

// ---------------- per-row max / logsumexp (online, one pass) ----------------
__device__ __forceinline__ void ms_combine(float& m, float& s, float m2, float s2) {
    float M = fmaxf(m, m2);
    s = s * expf(m - M) + s2 * expf(m2 - M);
    m = M;
}
__global__ void k_row_reduce(const float* __restrict__ C) {
    __shared__ float sm[8], ss[8];
    int row = blockIdx.x, tid = threadIdx.x;
    const float* p = C + (long)row * VV;
    float m = -1e30f, s = 0.f;
    for (int n = tid; n < VV; n += 256) {
        float x = p[n];
        float M = fmaxf(m, x);
        s = s * expf(m - M) + expf(x - M);
        m = M;
    }
    #pragma unroll
    for (int o = 16; o; o >>= 1) {
        float m2 = __shfl_xor_sync(0xffffffffu, m, o);
        float s2 = __shfl_xor_sync(0xffffffffu, s, o);
        ms_combine(m, s, m2, s2);
    }
    int w = tid >> 5;
    if ((tid & 31) == 0) { sm[w] = m; ss[w] = s; }
    __syncthreads();
    if (tid == 0) {
        m = sm[0]; s = ss[0];
        for (int i = 1; i < 8; i++) ms_combine(m, s, sm[i], ss[i]);
        g_rowmax[row] = m;
        g_rowlse[row] = logf(s);
    }
}

// ---------------- apply log_softmax in place (float4) ----------------
__global__ void k_lsm(float* __restrict__ C) {
    long i = (long)blockIdx.x * blockDim.x + threadIdx.x;   // float4 index, exact grid
    int row = (int)(i / (VV/4));
    float sub = g_rowmax[row] + g_rowlse[row];
    float4* p = (float4*)C;
    float4 v = p[i];
    v.x -= sub; v.y -= sub; v.z -= sub; v.w -= sub;
    p[i] = v;
}

// ---------------- launch ----------------
extern "C" void kernel_launch(void* const* d_in, const int* in_sizes, int n_in,
                              void* d_out, int out_size) {
    const int*   inp     = (const int*)  d_in[0];
    const int*   tar     = (const int*)  d_in[1];
    const float* enc_emb = (const float*)d_in[2];
    const float* dec_emb = (const float*)d_in[3];
    const float* Wih_f   = (const float*)d_in[4];
    const float* Whh_f   = (const float*)d_in[5];
    const float* b_f     = (const float*)d_in[6];
    const float* Wih_b   = (const float*)d_in[7];
    const float* Whh_b   = (const float*)d_in[8];
    const float* b_b     = (const float*)d_in[9];
    const float* Wa      = (const float*)d_in[10];
    const float* va      = (const float*)d_in[11];
    const float* Wih_d   = (const float*)d_in[12];
    const float* Whh_d   = (const float*)d_in[13];
    const float* b_d     = (const float*)d_in[14];
    const float* Wout    = (const float*)d_in[15];
    const float* bout    = (const float*)d_in[16];
    float* out = (float*)d_out;

    static bf16 *sp_embsrc=nullptr, *sp_embtgt, *sp_wihfb, *sp_wihbb, *sp_whhfb, *sp_whhbb,
                *sp_wih1db, *sp_wih2db, *sp_whhdb, *sp_wa1b, *sp_wa2b, *sp_woutb,
                *sp_encoutb, *sp_hsb;
    static float *sp_gxe, *sp_gxd, *sp_encproj;
    if (!sp_embsrc) {
        cudaGetSymbolAddress((void**)&sp_embsrc,  g_emb_srcb);
        cudaGetSymbolAddress((void**)&sp_embtgt,  g_emb_tgtb);
        cudaGetSymbolAddress((void**)&sp_wihfb,   g_wihfb);
        cudaGetSymbolAddress((void**)&sp_wihbb,   g_wihbb);
        cudaGetSymbolAddress((void**)&sp_whhfb,   g_whhfb);
        cudaGetSymbolAddress((void**)&sp_whhbb,   g_whhbb);
        cudaGetSymbolAddress((void**)&sp_wih1db,  g_wih1db);
        cudaGetSymbolAddress((void**)&sp_wih2db,  g_wih2db);
        cudaGetSymbolAddress((void**)&sp_whhdb,   g_whhdb);
        cudaGetSymbolAddress((void**)&sp_wa1b,    g_wa1b);
        cudaGetSymbolAddress((void**)&sp_wa2b,    g_wa2b);
        cudaGetSymbolAddress((void**)&sp_woutb,   g_woutb);
        cudaGetSymbolAddress((void**)&sp_encoutb, g_enc_outb);
        cudaGetSymbolAddress((void**)&sp_hsb,     g_hsb);
        cudaGetSymbolAddress((void**)&sp_gxe,     g_gxe);
        cudaGetSymbolAddress((void**)&sp_gxd,     g_gxd);
        cudaGetSymbolAddress((void**)&sp_encproj, g_encproj);
    }

    // embeddings + state init
    k_embed<<<(2*TS*BB*EE)/256, 256>>>(inp, tar, enc_emb, dec_emb);
    k_init<<<(BB*HH)/256, 256>>>();

    // weight conversions (contiguous)
    k_cvt_contig<<<(4*HH*EE/4)/256, 256>>>(Wih_f, sp_wihfb);
    k_cvt_contig<<<(4*HH*HH/4)/256, 256>>>(Whh_f, sp_whhfb);
    k_cvt_contig<<<(4*HH*EE/4)/256, 256>>>(Wih_b, sp_wihbb);
    k_cvt_contig<<<(4*HH*HH/4)/256, 256>>>(Whh_b, sp_whhbb);
    k_cvt_contig<<<(int)(((long)4*DH*DH/4)/256), 256>>>(Whh_d, sp_whhdb);
    k_cvt_contig<<<(int)(((long)VV*DH/4)/256), 256>>>(Wout, sp_woutb);
    // strided slices
    k_cvt_strided<<<(int)(((long)4*DH*EE/2)/256), 256>>>(Wih_d, sp_wih1db, EE+2*HH+DH-DH, 0, EE);     // srcld=1536
    k_cvt_strided<<<(int)(((long)4*DH*DH/2)/256), 256>>>(Wih_d, sp_wih2db, 1536, EE, DH);
    k_cvt_strided<<<((DH*DH)/2)/256, 256>>>(Wa, sp_wa1b, 2*DH, 0,  DH);
    k_cvt_strided<<<((DH*DH)/2)/256, 256>>>(Wa, sp_wa2b, 2*DH, DH, DH);

    // precompute input-side gate contributions (bf16 MMA)
    hgemm_abt<<<dim3((4*HH)/128, (TS*BB)/128), 256>>>(sp_embsrc, EE, sp_wihfb, EE,
                                                      nullptr, sp_gxe, 4*HH, EE, 0);
    hgemm_abt<<<dim3((4*HH)/128, (TS*BB)/128), 256>>>(sp_embsrc, EE, sp_wihbb, EE,
                                                      nullptr, sp_gxe + (long)TS*BB*4*HH, 4*HH, EE, 0);
    hgemm_abt<<<dim3((4*DH)/128, (TT*BB)/128), 256>>>(sp_embtgt, EE, sp_wih1db, EE,
                                                      nullptr, sp_gxd, 4*DH, EE, 0);

    // encoder BiLSTM, 64 steps
    for (int t = 0; t < TS; t++) {
        k_enc_hgemm<<<dim3(16, 2, 2), 256>>>(t);
        k_enc_point<<<(2*BB*HH/2)/64, 64>>>(b_f, b_b, t);
    }

    // decoder init + attention precompute: enc_proj = enc_out @ Wa2^T
    k_dec_init<<<(BB*DH)/256, 256>>>();
    hgemm_abt<<<dim3(DH/128, (TS*BB)/128), 256>>>(sp_encoutb, DH, sp_wa2b, DH,
                                                  nullptr, sp_encproj, DH, DH, 0);

    // decoder, 64 steps
    for (int t = 0; t < TT; t++) {
        k_dec_hgemm1<<<dim3(ND1/128, 4), 256>>>(t);
        k_attn<<<BB, 256>>>(va);
        k_dec_hgemm2<<<dim3((4*DH)/128, 4), 256>>>();
        k_dec_point<<<(BB*DH/2)/64, 64>>>(b_d, t);
    }

    // output projection + relu (bf16 MMA), then log_softmax
    hgemm_abt<<<dim3(VV/128, MOUT/128), 256>>>(sp_hsb, DH, sp_woutb, DH,
                                               bout, out, VV, DH, 1);
    k_row_reduce<<<MOUT, 256>>>(out);
    k_lsm<<<(int)(((long)MOUT*VV/4)/256), 256>>>(out);
}

// round 13
// speedup vs baseline: 3.5096x; 1.0629x over previous
#include <cuda_runtime.h>
#include <cuda_bf16.h>
#include <math.h>

// ---------------- problem constants ----------------
#define BB   32          // batch
#define TS   64          // T_src
#define TT   64          // T_tgt
#define EE   512         // embedding dim
#define HH   512         // encoder hidden (per direction)
#define DH   1024        // decoder hidden (= 2H)
#define VV   32000       // vocab
#define MOUT (BB*TT)     // 2048 output rows
#define ND1  (4*DH + DH) // merged decoder gemm1 width: 4096 gates + 1024 hq = 5120

#define NB_ENC 64        // persistent encoder grid (<= 148 SMs, co-resident)
#define NB_DEC 128       // persistent decoder grid

typedef unsigned int u32;
typedef __nv_bfloat16 bf16;

// ---------------- device scratch (no allocs allowed) ----------------
__device__ bf16  g_emb_srcb[TS*BB*EE];
__device__ bf16  g_emb_tgtb[TT*BB*EE];
__device__ float g_enc_out [TS*BB*DH];
__device__ bf16  g_enc_outb[TS*BB*DH];
__device__ float g_encproj [TS*BB*DH];
// bf16 weights (converted once)
__device__ bf16 g_wihfb[4*HH*EE];
__device__ bf16 g_whhfb[4*HH*HH];
__device__ bf16 g_wihbb[4*HH*EE];
__device__ bf16 g_whhbb[4*HH*HH];
__device__ bf16 g_wih1db[(long)4*DH*EE];   // Wih_d[:, 0:512]
__device__ bf16 g_wih2db[(long)4*DH*DH];   // Wih_d[:, 512:1536]
__device__ bf16 g_whhdb[(long)4*DH*DH];
__device__ bf16 g_wa1b[DH*DH];             // Wa[:, 0:DH]
__device__ bf16 g_wa2b[DH*DH];             // Wa[:, DH:2DH]
__device__ bf16 g_woutb[(long)VV*DH];
// precomputed input-side gate contributions (fp32)
__device__ float g_gxe[2][TS*BB][4*HH];    // encoder emb@Wih^T per dir
__device__ float g_gxd[TT*BB][4*DH];       // decoder emb@Wih1^T
// recurrent states
__device__ bf16  g_hfb[2][BB*HH];
__device__ bf16  g_hbb[2][BB*HH];
__device__ float g_cf[BB*HH];
__device__ float g_cb[BB*HH];
__device__ bf16  g_dhb[2][BB*DH];
__device__ float g_dc[BB*DH];
__device__ bf16  g_cvecb[BB*DH];
__device__ bf16  g_hsb[BB*TT*DH];
__device__ float g_rowmax[MOUT];
__device__ float g_rowlse[MOUT];
// K-split partial accumulators (fp32)
__device__ float g_pe[2][2][BB][4*HH];     // encoder: dir x 2 k-splits
__device__ float g_pd1[2][BB][ND1];        // decoder h-gemm (gates + hq), 2 k-splits
__device__ float g_pd2[4][BB][4*DH];       // decoder cvec-gemm, 4 k-splits
// software grid barrier state
__device__ unsigned g_barc = 0;
__device__ unsigned g_bars = 0;

// ---------------- helpers ----------------
__device__ __forceinline__ float warp_sum(float v) {
    #pragma unroll
    for (int o = 16; o; o >>= 1) v += __shfl_xor_sync(0xffffffffu, v, o);
    return v;
}
__device__ __forceinline__ float sigmoidf(float x) { return 1.f / (1.f + expf(-x)); }
__device__ __forceinline__ float tanh_fast(float x) {
    float y; asm("tanh.approx.f32 %0, %1;" : "=f"(y) : "f"(x)); return y;
}
__device__ __forceinline__ void mma_bf16(float& c0, float& c1, float& c2, float& c3,
                                         u32 a0, u32 a1, u32 a2, u32 a3,
                                         u32 b0, u32 b1) {
    asm("mma.sync.aligned.m16n8k16.row.col.f32.bf16.bf16.f32 "
        "{%0,%1,%2,%3},{%4,%5,%6,%7},{%8,%9},{%0,%1,%2,%3};"
        : "+f"(c0), "+f"(c1), "+f"(c2), "+f"(c3)
        : "r"(a0), "r"(a1), "r"(a2), "r"(a3), "r"(b0), "r"(b1));
}
__device__ __forceinline__ void stcg_bf2(bf16* p, __nv_bfloat162 v) {
    __stcg((u32*)p, *(u32*)&v);
}

// ---------------- software grid barrier (sense = monotonic counter) --------
__device__ __forceinline__ void gbar(unsigned nb, unsigned& sense) {
    sense += 1;
    __threadfence();              // every thread: flush my writes to L2
    __syncthreads();
    if (threadIdx.x == 0) {
        if (atomicAdd(&g_barc, 1u) == nb - 1u) {
            atomicExch(&g_barc, 0u);
            __threadfence();
            atomicExch(&g_bars, sense);
        } else {
            while (*(volatile unsigned*)&g_bars != sense) {}
        }
    }
    __syncthreads();
}

// ---------------- embedding gather (src + tgt) -> bf16 ----------------
__global__ void k_embed(const int* __restrict__ inp, const int* __restrict__ tar,
                        const float* __restrict__ enc_emb, const float* __restrict__ dec_emb) {
    int i = blockIdx.x * blockDim.x + threadIdx.x;     // exact grid: 2*TS*BB*EE
    const int n1 = TS * BB * EE;
    if (i < n1) {
        int t = i / (BB*EE); int r = i - t*(BB*EE); int b = r / EE; int e = r - b*EE;
        g_emb_srcb[i] = __float2bfloat16(enc_emb[(long)inp[b*TS + t] * EE + e]);
    } else {
        int j = i - n1;
        int t = j / (BB*EE); int r = j - t*(BB*EE); int b = r / EE; int e = r - b*EE;
        g_emb_tgtb[j] = __float2bfloat16(dec_emb[(long)tar[b*TT + t] * EE + e]);
    }
}

// ---------------- conversions fp32 -> bf16 ----------------
__global__ void k_cvt_contig(const float* __restrict__ src, bf16* __restrict__ dst) {
    long i = (long)blockIdx.x * blockDim.x + threadIdx.x;    // per float4, exact grid
    float4 v = ((const float4*)src)[i];
    __nv_bfloat162* o = (__nv_bfloat162*)dst;
    o[i*2]   = __floats2bfloat162_rn(v.x, v.y);
    o[i*2+1] = __floats2bfloat162_rn(v.z, v.w);
}
__global__ void k_cvt_strided(const float* __restrict__ src, bf16* __restrict__ dst,
                              int srcld, int coloff, int outw) {
    long i = (long)blockIdx.x * blockDim.x + threadIdx.x;    // per float2, exact grid
    int row = (int)(i / (outw/2));
    int col = (int)(i % (outw/2)) * 2;
    float2 v = *(const float2*)&src[(long)row*srcld + coloff + col];
    *(__nv_bfloat162*)&dst[(long)row*outw + col] = __floats2bfloat162_rn(v.x, v.y);
}

// =====================================================================
// skinny bf16 GEMM core: out[32, 128] (fp32) = X[32, kslice] @ W[128, kslice]^T
// 256 threads = 8 warps (2m x 4n); BK=32, smem stride 40 bf16.
// X via __ldcg (cross-block, L2-coherent); W via normal LDG (L1-resident
// across persistent-loop iterations); out via __stcg.
// =====================================================================
__device__ __forceinline__ void hg32_core(
    const bf16* __restrict__ X, int xld,
    const bf16* __restrict__ W, int wld,
    int kslice, float* __restrict__ out, int ldc,
    bf16* Xs, bf16* Ws)
{
    int tid = threadIdx.x;
    int warp = tid >> 5, lane = tid & 31;
    int wm = warp & 1, wn = warp >> 1;
    int grp = lane >> 2, tg = lane & 3;
    uint4* Xs4 = (uint4*)Xs;
    uint4* Ws4 = (uint4*)Ws;

    float acc[4][4];
    #pragma unroll
    for (int nt = 0; nt < 4; nt++)
        #pragma unroll
        for (int q = 0; q < 4; q++) acc[nt][q] = 0.f;

    for (int k0 = 0; k0 < kslice; k0 += 32) {
        #pragma unroll
        for (int u = 0; u < 2; u++) {
            int idx = tid + u*256;
            int row = idx >> 2, c8 = (idx & 3) * 8;
            Ws4[row*5 + (c8 >> 3)] = *(const uint4*)(W + (long)row*wld + k0 + c8);
        }
        if (tid < 128) {
            int row = tid >> 2, c8 = (tid & 3) * 8;
            Xs4[row*5 + (c8 >> 3)] = __ldcg((const uint4*)(X + (long)row*xld + k0 + c8));
        }
        __syncthreads();
        #pragma unroll
        for (int ks = 0; ks < 2; ks++) {
            int kof = ks*16 + tg*2;
            int m0 = wm*16 + grp;
            u32 a0 = *(const u32*)&Xs[m0*40 + kof];
            u32 a1 = *(const u32*)&Xs[(m0+8)*40 + kof];
            u32 a2 = *(const u32*)&Xs[m0*40 + kof + 8];
            u32 a3 = *(const u32*)&Xs[(m0+8)*40 + kof + 8];
            #pragma unroll
            for (int nt = 0; nt < 4; nt++) {
                int n0 = wn*32 + nt*8 + grp;
                u32 b0 = *(const u32*)&Ws[n0*40 + kof];
                u32 b1 = *(const u32*)&Ws[n0*40 + kof + 8];
                mma_bf16(acc[nt][0], acc[nt][1], acc[nt][2], acc[nt][3],
                         a0, a1, a2, a3, b0, b1);
            }
        }
        __syncthreads();
    }
    int m0 = wm*16 + grp;
    #pragma unroll
    for (int nt = 0; nt < 4; nt++) {
        int n = wn*32 + nt*8 + tg*2;
        __stcg((float2*)&out[(long)m0*ldc + n],     make_float2(acc[nt][0], acc[nt][1]));
        __stcg((float2*)&out[(long)(m0+8)*ldc + n], make_float2(acc[nt][2], acc[nt][3]));
    }
}

// =====================================================================
// persistent encoder loop: 64 blocks, 2 barriers per step
// =====================================================================
__global__ void __launch_bounds__(256, 1)
k_enc_loop(const float* __restrict__ b_f, const float* __restrict__ b_b) {
    __shared__ __align__(16) bf16 Xs[32*40];
    __shared__ __align__(16) bf16 Ws[128*40];
    int bid = blockIdx.x, tid = threadIdx.x;
    unsigned sense = *(volatile unsigned*)&g_bars;

    int dir = bid >> 5, rem = bid & 31, sp = rem >> 4, ct = rem & 15;
    int c0 = ct * 128, k0 = sp * 256;
    const bf16* Whh = (dir ? g_whhbb : g_whhfb) + (long)c0*HH + k0;

    // point-phase element mapping (fixed per thread -> c stays L1-private)
    int pi  = bid*256 + tid;          // 0..16383
    int pdir = pi >> 13;
    int prem = pi & 8191;
    int pb  = prem >> 8;              // /(HH/2)
    int pj  = (prem & 255) * 2;
    float* cbuf = (pdir ? g_cb : g_cf) + pb*HH;
    const float* bias = pdir ? b_b : b_f;

    // init h=0, c=0 (same mapping as point phase)
    {
        __nv_bfloat162 z = __floats2bfloat162_rn(0.f, 0.f);
        stcg_bf2(((pdir ? g_hbb[0] : g_hfb[0]) + pb*HH) + pj, z);
        *(float2*)&cbuf[pj] = make_float2(0.f, 0.f);
    }
    gbar(NB_ENC, sense);

    for (int t = 0; t < TS; t++) {
        // ---- gemm phase: gates_h partial = h @ Whh^T (one tile per block)
        const bf16* X = (dir ? g_hbb[t & 1] : g_hfb[t & 1]) + k0;
        hg32_core(X, HH, Whh, HH, 256, &g_pe[dir][sp][0][0] + c0, 4*HH, Xs, Ws);
        gbar(NB_ENC, sense);

        // ---- point phase
        {
            int pos = pdir ? (TS-1-t) : t;
            const float* gx = &g_gxe[pdir][pos*BB + pb][0];
            float2 g0 = *(const float2*)&bias[0*HH + pj];
            float2 g1 = *(const float2*)&bias[1*HH + pj];
            float2 g2 = *(const float2*)&bias[2*HH + pj];
            float2 g3 = *(const float2*)&bias[3*HH + pj];
            float2 v;
            v = *(const float2*)&gx[0*HH + pj]; g0.x += v.x; g0.y += v.y;
            v = *(const float2*)&gx[1*HH + pj]; g1.x += v.x; g1.y += v.y;
            v = *(const float2*)&gx[2*HH + pj]; g2.x += v.x; g2.y += v.y;
            v = *(const float2*)&gx[3*HH + pj]; g3.x += v.x; g3.y += v.y;
            #pragma unroll
            for (int s = 0; s < 2; s++) {
                const float* p = &g_pe[pdir][s][pb][0];
                v = __ldcg((const float2*)&p[0*HH + pj]); g0.x += v.x; g0.y += v.y;
                v = __ldcg((const float2*)&p[1*HH + pj]); g1.x += v.x; g1.y += v.y;
                v = __ldcg((const float2*)&p[2*HH + pj]); g2.x += v.x; g2.y += v.y;
                v = __ldcg((const float2*)&p[3*HH + pj]); g3.x += v.x; g3.y += v.y;
            }
            float2 cc = *(float2*)&cbuf[pj];
            float2 c, h;
            c.x = sigmoidf(g1.x) * cc.x + sigmoidf(g0.x) * tanhf(g2.x);
            c.y = sigmoidf(g1.y) * cc.y + sigmoidf(g0.y) * tanhf(g2.y);
            h.x = sigmoidf(g3.x) * tanhf(c.x);
            h.y = sigmoidf(g3.y) * tanhf(c.y);
            *(float2*)&cbuf[pj] = c;
            bf16* hnext = (pdir ? g_hbb[(t+1) & 1] : g_hfb[(t+1) & 1]) + pb*HH;
            stcg_bf2(&hnext[pj], __floats2bfloat162_rn(h.x, h.y));
            long oidx = ((long)pos*BB + pb)*DH + pdir*HH + pj;
            *(float2*)&g_enc_out[oidx] = h;
            *(__nv_bfloat162*)&g_enc_outb[oidx] = __floats2bfloat162_rn(h.x, h.y);
        }
        gbar(NB_ENC, sense);
    }
}

// =====================================================================
// persistent decoder loop: 128 blocks, init + 4 barriers per step
// =====================================================================
__global__ void __launch_bounds__(256, 1)
k_dec_loop(const float* __restrict__ va, const float* __restrict__ b_d) {
    __shared__ __align__(16) bf16 Xs[32*40];
    __shared__ __align__(16) bf16 Ws[128*40];
    __shared__ float s_hq[DH];
    __shared__ float s_sc[TS];
    __shared__ float s_inv;
    int bid = blockIdx.x, tid = threadIdx.x;
    unsigned sense = *(volatile unsigned*)&g_bars;

    // gemm1 tile (blocks 0..79): 40 col-tiles x 2 k-splits, kslice 512
    int g1c0 = (bid % 40) * 128, g1sp = bid / 40, g1k0 = g1sp * 512;
    const bf16* g1W = (g1c0 < 4*DH) ? (g_whhdb + (long)g1c0*DH + g1k0)
                                    : (g_wa1b + (long)(g1c0 - 4*DH)*DH + g1k0);
    // gemm2 tile (all 128 blocks): 32 col-tiles x 4 k-splits, kslice 256
    int g2c0 = (bid & 31) * 128, g2sp = bid >> 5, g2k0 = g2sp * 256;
    const bf16* g2W = g_wih2db + (long)g2c0*DH + g2k0;

    // point/init mapping (fixed -> g_dc stays L1-private)
    int pi = bid*256 + tid;
    int pb = pi >> 9;                  // /(DH/2)
    int pj = (pi & 511) * 2;
    bool pact = pi < BB*DH/2;

    // ---- init: concat encoder final states
    if (pact) {
        __nv_bfloat162 h; float2 c;
        if (pj < HH) {
            h = __floats2bfloat162_rn(__bfloat162float(g_hfb[0][pb*HH + pj]),
                                      __bfloat162float(g_hfb[0][pb*HH + pj + 1]));
            c = make_float2(g_cf[pb*HH + pj], g_cf[pb*HH + pj + 1]);
        } else {
            h = __floats2bfloat162_rn(__bfloat162float(g_hbb[0][pb*HH + pj - HH]),
                                      __bfloat162float(g_hbb[0][pb*HH + pj - HH + 1]));
            c = make_float2(g_cb[pb*HH + pj - HH], g_cb[pb*HH + pj - HH + 1]);
        }
        stcg_bf2(&g_dhb[0][pb*DH + pj], h);
        *(float2*)&g_dc[pb*DH + pj] = c;
    }
    gbar(NB_DEC, sense);

    for (int t = 0; t < TT; t++) {
        // ---- gemm1: [gates_h | hq] = h @ [Whh_d | Wa1]^T
        if (bid < 80) {
            hg32_core(g_dhb[t & 1] + g1k0, DH, g1W, DH, 512,
                      &g_pd1[g1sp][0][0] + g1c0, ND1, Xs, Ws);
        }
        gbar(NB_DEC, sense);

        // ---- attention (blocks 0..31, one per batch row)
        if (bid < BB) {
            int b = bid;
            for (int o = tid; o < DH; o += 256) {
                float v = __ldcg(&g_pd1[0][b][4*DH + o]) + __ldcg(&g_pd1[1][b][4*DH + o]);
                s_hq[o] = v;
            }
            __syncthreads();
            int w = tid >> 5, lane = tid & 31;
            for (int ts = w; ts < TS; ts += 8) {
                const float* ep = g_encproj + ((long)ts*BB + b)*DH;
                float s = 0.f;
                for (int o = lane; o < DH; o += 32) s += va[o] * tanh_fast(s_hq[o] + ep[o]);
                s = warp_sum(s);
                if (lane == 0) s_sc[ts] = s;
            }
            __syncthreads();
            if (tid == 0) {
                float m = -1e30f;
                for (int i = 0; i < TS; i++) m = fmaxf(m, s_sc[i]);
                float s = 0.f;
                for (int i = 0; i < TS; i++) { float e = expf(s_sc[i] - m); s_sc[i] = e; s += e; }
                s_inv = 1.f / s;
            }
            __syncthreads();
            float inv = s_inv;
            for (int o = tid*2; o < DH; o += 512) {     // 256 threads x 2 cols (even o!)
                float a0 = 0.f, a1 = 0.f;
                #pragma unroll 4
                for (int ts = 0; ts < TS; ts++) {
                    float2 e = *(const float2*)&g_enc_out[((long)ts*BB + b)*DH + o];
                    a0 += s_sc[ts] * e.x; a1 += s_sc[ts] * e.y;
                }
                stcg_bf2(&g_cvecb[b*DH + o], __floats2bfloat162_rn(a0 * inv, a1 * inv));
            }
        }
        gbar(NB_DEC, sense);

        // ---- gemm2: gates_c = cvec @ Wih2^T
        hg32_core(g_cvecb + g2k0, DH, g2W, DH, 256,
                  &g_pd2[g2sp][0][0] + g2c0, 4*DH, Xs, Ws);
        gbar(NB_DEC, sense);

        // ---- point
        if (pact) {
            const float* gx = &g_gxd[t*BB + pb][0];
            float2 g0 = *(const float2*)&b_d[0*DH + pj];
            float2 g1 = *(const float2*)&b_d[1*DH + pj];
            float2 g2 = *(const float2*)&b_d[2*DH + pj];
            float2 g3 = *(const float2*)&b_d[3*DH + pj];
            float2 v;
            v = *(const float2*)&gx[0*DH + pj]; g0.x += v.x; g0.y += v.y;
            v = *(const float2*)&gx[1*DH + pj]; g1.x += v.x; g1.y += v.y;
            v = *(const float2*)&gx[2*DH + pj]; g2.x += v.x; g2.y += v.y;
            v = *(const float2*)&gx[3*DH + pj]; g3.x += v.x; g3.y += v.y;
            #pragma unroll
            for (int s = 0; s < 2; s++) {
                const float* p1 = &g_pd1[s][pb][0];
                v = __ldcg((const float2*)&p1[0*DH + pj]); g0.x += v.x; g0.y += v.y;
                v = __ldcg((const float2*)&p1[1*DH + pj]); g1.x += v.x; g1.y += v.y;
                v = __ldcg((const float2*)&p1[2*DH + pj]); g2.x += v.x; g2.y += v.y;
                v = __ldcg((const float2*)&p1[3*DH + pj]); g3.x += v.x; g3.y += v.y;
            }
            #pragma unroll
            for (int s = 0; s < 4; s++) {
                const float* p2 = &g_pd2[s][pb][0];
                v = __ldcg((const float2*)&p2[0*DH + pj]); g0.x += v.x; g0.y += v.y;
                v = __ldcg((const float2*)&p2[1*DH + pj]); g1.x += v.x; g1.y += v.y;
                v = __ldcg((const float2*)&p2[2*DH + pj]); g2.x += v.x; g2.y += v.y;
                v = __ldcg((const float2*)&p2[3*DH + pj]); g3.x += v.x; g3.y += v.y;
            }
            long si = (long)pb*DH + pj;
            float2 cc = *(float2*)&g_dc[si];
            float2 c, h;
            c.x = sigmoidf(g1.x) * cc.x + sigmoidf(g0.x) * tanhf(g2.x);
            c.y = sigmoidf(g1.y) * cc.y + sigmoidf(g0.y) * tanhf(g2.y);
            h.x = sigmoidf(g3.x) * tanhf(c.x);
            h.y = sigmoidf(g3.y) * tanhf(c.y);
            *(float2*)&g_dc[si] = c;
            stcg_bf2(&g_dhb[(t+1) & 1][si], __floats2bfloat162_rn(h.x, h.y));
            *(__nv_bfloat162*)&g_hsb[((long)pb*TT + t)*DH + pj] = __floats2bfloat162_rn(h.x, h.y);
        }
        gbar(NB_DEC, sense);
    }
}

// =====================================================================
// bf16 tensor-core GEMM: C[M,N] = A[M,K] @ B[N,K]^T (+bias, +relu), fp32 C
// 128x128 block tile, BK=32, 256 threads; validated in R10/R11.
// =====================================================================
__global__ void hgemm_abt(const bf16* __restrict__ A, int lda,
                          const bf16* __restrict__ B, int ldb,
                          const float* __restrict__ bias,
                          float* __restrict__ C, int ldc,
                          int K, int do_relu) {
    __shared__ __align__(16) bf16 As[128*40];
    __shared__ __align__(16) bf16 Bs[128*40];
    int tid = threadIdx.x;
    int bm = blockIdx.y, bn = blockIdx.x;
    int warp = tid >> 5, lane = tid & 31;
    int wm = warp & 1, wn = warp >> 1;
    int grp = lane >> 2, tg = lane & 3;

    const bf16* Ag = A + (long)bm*128*lda;
    const bf16* Bg = B + (long)bn*128*ldb;
    uint4* As4 = (uint4*)As;
    uint4* Bs4 = (uint4*)Bs;

    float acc[4][4][4];
    #pragma unroll
    for (int mt = 0; mt < 4; mt++)
        #pragma unroll
        for (int nt = 0; nt < 4; nt++)
            #pragma unroll
            for (int q = 0; q < 4; q++) acc[mt][nt][q] = 0.f;

    for (int k0 = 0; k0 < K; k0 += 32) {
        #pragma unroll
        for (int u = 0; u < 2; u++) {
            int idx = tid + u*256;
            int row = idx >> 2, c8 = (idx & 3) * 8;
            As4[row*5 + (c8 >> 3)] = *(const uint4*)(Ag + (long)row*lda + k0 + c8);
            Bs4[row*5 + (c8 >> 3)] = *(const uint4*)(Bg + (long)row*ldb + k0 + c8);
        }
        __syncthreads();
        #pragma unroll
        for (int ks = 0; ks < 2; ks++) {
            int kof = ks*16 + tg*2;
            u32 af[4][4], bf[4][2];
            #pragma unroll
            for (int mt = 0; mt < 4; mt++) {
                int m0 = wm*64 + mt*16 + grp;
                af[mt][0] = *(const u32*)&As[(m0    )*40 + kof    ];
                af[mt][1] = *(const u32*)&As[(m0 + 8)*40 + kof    ];
                af[mt][2] = *(const u32*)&As[(m0    )*40 + kof + 8];
                af[mt][3] = *(const u32*)&As[(m0 + 8)*40 + kof + 8];
            }
            #pragma unroll
            for (int nt = 0; nt < 4; nt++) {
                int n0 = wn*32 + nt*8 + grp;
                bf[nt][0] = *(const u32*)&Bs[n0*40 + kof    ];
                bf[nt][1] = *(const u32*)&Bs[n0*40 + kof + 8];
            }
            #pragma unroll
            for (int mt = 0; mt < 4; mt++)
                #pragma unroll
                for (int nt = 0; nt < 4; nt++)
                    mma_bf16(acc[mt][nt][0], acc[mt][nt][1], acc[mt][nt][2], acc[mt][nt][3],
                             af[mt][0], af[mt][1], af[mt][2], af[mt][3],
                             bf[nt][0], bf[nt][1]);
        }
        __syncthreads();
    }

    #pragma unroll
    for (int mt = 0; mt < 4; mt++) {
        long m = (long)bm*128 + wm*64 + mt*16 + grp;
        #pragma unroll
        for (int nt = 0; nt < 4; nt++) {
            int n = bn*128 + wn*32 + nt*8 + tg*2;
            float2 v0 = make_float2(acc[mt][nt][0], acc[mt][nt][1]);
            float2 v1 = make_float2(acc[mt][nt][2], acc[mt][nt][3]);
            if (bias) {
                float2 bb = *(const float2*)&bias[n];
                v0.x += bb.x; v0.y += bb.y; v1.x += bb.x; v1.y += bb.y;
            }
            if (do_relu) {
                v0.x = fmaxf(v0.x, 0.f); v0.y = fmaxf(v0.y, 0.f);
                v1.x = fmaxf(v1.x, 0.f); v1.y = fmaxf(v1.y, 0.f);
            }
            *(float2*)&C[m*ldc + n]     = v0;
            *(float2*)&C[(m+8)*ldc + n] = v1;
        }
    }
}

// ---------------- per-row max / logsumexp (online, one pass) ----------------
__device__ __forceinline__ void ms_combine(float& m, float& s, float m2, float s2) {
    float M = fmaxf(m, m2);
    s = s * expf(m - M) + s2 * expf(m2 - M);
    m = M;
}
__global__ void k_row_reduce(const float* __restrict__ C) {
    __shared__ float sm[8], ss[8];
    int row = blockIdx.x, tid = threadIdx.x;
    const float* p = C + (long)row * VV;
    float m = -1e30f, s = 0.f;
    for (int n = tid; n < VV; n += 256) {
        float x = p[n];
        float M = fmaxf(m, x);
        s = s * expf(m - M) + expf(x - M);
        m = M;
    }
    #pragma unroll
    for (int o = 16; o; o >>= 1) {
        float m2 = __shfl_xor_sync(0xffffffffu, m, o);
        float s2 = __shfl_xor_sync(0xffffffffu, s, o);
        ms_combine(m, s, m2, s2);
    }
    int w = tid >> 5;
    if ((tid & 31) == 0) { sm[w] = m; ss[w] = s; }
    __syncthreads();
    if (tid == 0) {
        m = sm[0]; s = ss[0];
        for (int i = 1; i < 8; i++) ms_combine(m, s, sm[i], ss[i]);
        g_rowmax[row] = m;
        g_rowlse[row] = logf(s);
    }
}

// ---------------- apply log_softmax in place (float4) ----------------
__global__ void k_lsm(float* __restrict__ C) {
    long i = (long)blockIdx.x * blockDim.x + threadIdx.x;   // float4 index, exact grid
    int row = (int)(i / (VV/4));
    float sub = g_rowmax[row] + g_rowlse[row];
    float4* p = (float4*)C;
    float4 v = p[i];
    v.x -= sub; v.y -= sub; v.z -= sub; v.w -= sub;
    p[i] = v;
}

// ---------------- launch ----------------
extern "C" void kernel_launch(void* const* d_in, const int* in_sizes, int n_in,
                              void* d_out, int out_size) {
    const int*   inp     = (const int*)  d_in[0];
    const int*   tar     = (const int*)  d_in[1];
    const float* enc_emb = (const float*)d_in[2];
    const float* dec_emb = (const float*)d_in[3];
    const float* Wih_f   = (const float*)d_in[4];
    const float* Whh_f   = (const float*)d_in[5];
    const float* b_f     = (const float*)d_in[6];
    const float* Wih_b   = (const float*)d_in[7];
    const float* Whh_b   = (const float*)d_in[8];
    const float* b_b     = (const float*)d_in[9];
    const float* Wa      = (const float*)d_in[10];
    const float* va      = (const float*)d_in[11];
    const float* Wih_d   = (const float*)d_in[12];
    const float* Whh_d   = (const float*)d_in[13];
    const float* b_d     = (const float*)d_in[14];
    const float* Wout    = (const float*)d_in[15];
    const float* bout    = (const float*)d_in[16];
    float* out = (float*)d_out;

    static bf16 *sp_embsrc=nullptr, *sp_embtgt, *sp_wihfb, *sp_wihbb,
                *sp_wih1db, *sp_wih2db, *sp_whhdb, *sp_wa1b, *sp_wa2b, *sp_woutb,
                *sp_encoutb, *sp_hsb, *sp_whhfb, *sp_whhbb;
    static float *sp_gxe, *sp_gxd, *sp_encproj;
    if (!sp_embsrc) {
        cudaGetSymbolAddress((void**)&sp_embsrc,  g_emb_srcb);
        cudaGetSymbolAddress((void**)&sp_embtgt,  g_emb_tgtb);
        cudaGetSymbolAddress((void**)&sp_wihfb,   g_wihfb);
        cudaGetSymbolAddress((void**)&sp_wihbb,   g_wihbb);
        cudaGetSymbolAddress((void**)&sp_whhfb,   g_whhfb);
        cudaGetSymbolAddress((void**)&sp_whhbb,   g_whhbb);
        cudaGetSymbolAddress((void**)&sp_wih1db,  g_wih1db);
        cudaGetSymbolAddress((void**)&sp_wih2db,  g_wih2db);
        cudaGetSymbolAddress((void**)&sp_whhdb,   g_whhdb);
        cudaGetSymbolAddress((void**)&sp_wa1b,    g_wa1b);
        cudaGetSymbolAddress((void**)&sp_wa2b,    g_wa2b);
        cudaGetSymbolAddress((void**)&sp_woutb,   g_woutb);
        cudaGetSymbolAddress((void**)&sp_encoutb, g_enc_outb);
        cudaGetSymbolAddress((void**)&sp_hsb,     g_hsb);
        cudaGetSymbolAddress((void**)&sp_gxe,     g_gxe);
        cudaGetSymbolAddress((void**)&sp_gxd,     g_gxd);
        cudaGetSymbolAddress((void**)&sp_encproj, g_encproj);
    }

    // embeddings + weight conversions
    k_embed<<<(2*TS*BB*EE)/256, 256>>>(inp, tar, enc_emb, dec_emb);
    k_cvt_contig<<<(4*HH*EE/4)/256, 256>>>(Wih_f, sp_wihfb);
    k_cvt_contig<<<(4*HH*HH/4)/256, 256>>>(Whh_f, sp_whhfb);
    k_cvt_contig<<<(4*HH*EE/4)/256, 256>>>(Wih_b, sp_wihbb);
    k_cvt_contig<<<(4*HH*HH/4)/256, 256>>>(Whh_b, sp_whhbb);
    k_cvt_contig<<<(int)(((long)4*DH*DH/4)/256), 256>>>(Whh_d, sp_whhdb);
    k_cvt_contig<<<(int)(((long)VV*DH/4)/256), 256>>>(Wout, sp_woutb);
    k_cvt_strided<<<(int)(((long)4*DH*EE/2)/256), 256>>>(Wih_d, sp_wih1db, 1536, 0, EE);
    k_cvt_strided<<<(int)(((long)4*DH*DH/2)/256), 256>>>(Wih_d, sp_wih2db, 1536, EE, DH);
    k_cvt_strided<<<((DH*DH)/2)/256, 256>>>(Wa, sp_wa1b, 2*DH, 0,  DH);
    k_cvt_strided<<<((DH*DH)/2)/256, 256>>>(Wa, sp_wa2b, 2*DH, DH, DH);

    // precompute input-side gate contributions (bf16 MMA)
    hgemm_abt<<<dim3((4*HH)/128, (TS*BB)/128), 256>>>(sp_embsrc, EE, sp_wihfb, EE,
                                                      nullptr, sp_gxe, 4*HH, EE, 0);
    hgemm_abt<<<dim3((4*HH)/128, (TS*BB)/128), 256>>>(sp_embsrc, EE, sp_wihbb, EE,
                                                      nullptr, sp_gxe + (long)TS*BB*4*HH, 4*HH, EE, 0);
    hgemm_abt<<<dim3((4*DH)/128, (TT*BB)/128), 256>>>(sp_embtgt, EE, sp_wih1db, EE,
                                                      nullptr, sp_gxd, 4*DH, EE, 0);

    // encoder BiLSTM: one persistent kernel (init + 64 steps)
    k_enc_loop<<<NB_ENC, 256>>>(b_f, b_b);

    // attention precompute: enc_proj = enc_out @ Wa2^T
    hgemm_abt<<<dim3(DH/128, (TS*BB)/128), 256>>>(sp_encoutb, DH, sp_wa2b, DH,
                                                  nullptr, sp_encproj, DH, DH, 0);

    // decoder: one persistent kernel (init + 64 steps)
    k_dec_loop<<<NB_DEC, 256>>>(va, b_d);

    // output projection + relu (bf16 MMA), then log_softmax
    hgemm_abt<<<dim3(VV/128, MOUT/128), 256>>>(sp_hsb, DH, sp_woutb, DH,
                                               bout, out, VV, DH, 1);
    k_row_reduce<<<MOUT, 256>>>(out);
    k_lsm<<<(int)(((long)MOUT*VV/4)/256), 256>>>(out);
}

// round 17
// speedup vs baseline: 3.6069x; 1.0277x over previous
#include <cuda_runtime.h>
#include <cuda_bf16.h>
#include <math.h>

// ---------------- problem constants ----------------
#define BB   32          // batch
#define TS   64          // T_src
#define TT   64          // T_tgt
#define EE   512         // embedding dim
#define HH   512         // encoder hidden (per direction)
#define DH   1024        // decoder hidden (= 2H)
#define VV   32000       // vocab
#define MOUT (BB*TT)     // 2048 output rows
#define ND1  (4*DH + DH) // merged decoder gemm1 width: 4096 gates + 1024 hq = 5120

#define NB_ENC 64        // persistent encoder grid (co-resident)
#define NB_DEC 128       // persistent decoder grid

typedef unsigned int u32;
typedef __nv_bfloat16 bf16;

// ---------------- device scratch (no allocs allowed) ----------------
__device__ bf16  g_emb_srcb[TS*BB*EE];
__device__ bf16  g_emb_tgtb[TT*BB*EE];
__device__ float g_enc_out [TS*BB*DH];
__device__ bf16  g_enc_outb[TS*BB*DH];
__device__ float g_encproj [TS*BB*DH];
// bf16 weights (converted once)
__device__ bf16 g_wihfb[4*HH*EE];
__device__ bf16 g_whhfb[4*HH*HH];
__device__ bf16 g_wihbb[4*HH*EE];
__device__ bf16 g_whhbb[4*HH*HH];
__device__ bf16 g_wih1db[(long)4*DH*EE];   // Wih_d[:, 0:512]
__device__ bf16 g_wih2db[(long)4*DH*DH];   // Wih_d[:, 512:1536]
__device__ bf16 g_whhdb[(long)4*DH*DH];
__device__ bf16 g_wa1b[DH*DH];             // Wa[:, 0:DH]
__device__ bf16 g_wa2b[DH*DH];             // Wa[:, DH:2DH]
__device__ bf16 g_woutb[(long)VV*DH];
// precomputed input-side gate contributions (fp32)
__device__ float g_gxe[2][TS*BB][4*HH];    // encoder emb@Wih^T per dir
__device__ float g_gxd[TT*BB][4*DH];       // decoder emb@Wih1^T
// recurrent states
__device__ bf16  g_hfb[2][BB*HH];
__device__ bf16  g_hbb[2][BB*HH];
__device__ float g_cf[BB*HH];
__device__ float g_cb[BB*HH];
__device__ bf16  g_dhb[2][BB*DH];
__device__ float g_dc[BB*DH];
__device__ bf16  g_cvecb[BB*DH];
__device__ bf16  g_hsb[BB*TT*DH];
__device__ float g_rowmax[MOUT];
__device__ float g_rowlse[MOUT];
// K-split partial accumulators (fp32)
__device__ float g_pe[2][2][BB][4*HH];     // encoder: dir x 2 k-splits
__device__ float g_pd1[2][BB][ND1];        // decoder h-gemm (gates + hq), 2 k-splits
__device__ float g_pd2[4][BB][4*DH];       // decoder cvec-gemm, 4 k-splits
// software grid barrier state (R13 single-counter version — proven)
__device__ unsigned g_barc = 0;
__device__ unsigned g_bars = 0;

// ---------------- helpers ----------------
__device__ __forceinline__ float warp_sum(float v) {
    #pragma unroll
    for (int o = 16; o; o >>= 1) v += __shfl_xor_sync(0xffffffffu, v, o);
    return v;
}
__device__ __forceinline__ float sigmoidf(float x) { return 1.f / (1.f + expf(-x)); }
__device__ __forceinline__ float tanh_fast(float x) {
    float y; asm("tanh.approx.f32 %0, %1;" : "=f"(y) : "f"(x)); return y;
}
__device__ __forceinline__ void mma_bf16(float& c0, float& c1, float& c2, float& c3,
                                         u32 a0, u32 a1, u32 a2, u32 a3,
                                         u32 b0, u32 b1) {
    asm("mma.sync.aligned.m16n8k16.row.col.f32.bf16.bf16.f32 "
        "{%0,%1,%2,%3},{%4,%5,%6,%7},{%8,%9},{%0,%1,%2,%3};"
        : "+f"(c0), "+f"(c1), "+f"(c2), "+f"(c3)
        : "r"(a0), "r"(a1), "r"(a2), "r"(a3), "r"(b0), "r"(b1));
}
__device__ __forceinline__ void stcg_bf2(bf16* p, __nv_bfloat162 v) {
    __stcg((u32*)p, *(u32*)&v);
}
// cp.async for the standalone hgemm only (no inter-block sync there)
__device__ __forceinline__ void cpa_ca(u32 s, const void* g) {
    asm volatile("cp.async.ca.shared.global [%0], [%1], 16;" :: "r"(s), "l"(g));
}
#define CPA_COMMIT() asm volatile("cp.async.commit_group;" ::: "memory")
#define CPA_WAIT1()  asm volatile("cp.async.wait_group 1;" ::: "memory")
#define CPA_WAIT0()  asm volatile("cp.async.wait_group 0;" ::: "memory")

// ---------------- software grid barrier (R13 proven version) --------
__device__ __forceinline__ void gbar(unsigned nb, unsigned& sense) {
    sense += 1;
    __threadfence();              // every thread: flush my writes to L2
    __syncthreads();
    if (threadIdx.x == 0) {
        if (atomicAdd(&g_barc, 1u) == nb - 1u) {
            atomicExch(&g_barc, 0u);
            __threadfence();
            atomicExch(&g_bars, sense);
        } else {
            while (*(volatile unsigned*)&g_bars != sense) {}
        }
    }
    __syncthreads();
}

// ---------------- embedding gather (src + tgt) -> bf16 ----------------
__global__ void k_embed(const int* __restrict__ inp, const int* __restrict__ tar,
                        const float* __restrict__ enc_emb, const float* __restrict__ dec_emb) {
    int i = blockIdx.x * blockDim.x + threadIdx.x;     // exact grid: 2*TS*BB*EE
    const int n1 = TS * BB * EE;
    if (i < n1) {
        int t = i / (BB*EE); int r = i - t*(BB*EE); int b = r / EE; int e = r - b*EE;
        g_emb_srcb[i] = __float2bfloat16(enc_emb[(long)inp[b*TS + t] * EE + e]);
    } else {
        int j = i - n1;
        int t = j / (BB*EE); int r = j - t*(BB*EE); int b = r / EE; int e = r - b*EE;
        g_emb_tgtb[j] = __float2bfloat16(dec_emb[(long)tar[b*TT + t] * EE + e]);
    }
}

// ---------------- conversions fp32 -> bf16 ----------------
__global__ void k_cvt_contig(const float* __restrict__ src, bf16* __restrict__ dst) {
    long i = (long)blockIdx.x * blockDim.x + threadIdx.x;    // per float4, exact grid
    float4 v = ((const float4*)src)[i];
    __nv_bfloat162* o = (__nv_bfloat162*)dst;
    o[i*2]   = __floats2bfloat162_rn(v.x, v.y);
    o[i*2+1] = __floats2bfloat162_rn(v.z, v.w);
}
__global__ void k_cvt_strided(const float* __restrict__ src, bf16* __restrict__ dst,
                              int srcld, int coloff, int outw) {
    long i = (long)blockIdx.x * blockDim.x + threadIdx.x;    // per float2, exact grid
    int row = (int)(i / (outw/2));
    int col = (int)(i % (outw/2)) * 2;
    float2 v = *(const float2*)&src[(long)row*srcld + coloff + col];
    *(__nv_bfloat162*)&dst[(long)row*outw + col] = __floats2bfloat162_rn(v.x, v.y);
}

// =====================================================================
// skinny bf16 GEMM core (R13 synchronous version — proven correct):
// out[32, 128] (fp32) = X[32, kslice] @ W[128, kslice]^T
// 256 threads = 8 warps (2m x 4n); BK=32, smem stride 40 bf16.
// X via __ldcg (cross-block, L2-coherent); W via normal LDG (L1-resident
// across persistent-loop iterations); out via __stcg.
// =====================================================================
__device__ __forceinline__ void hg32_core(
    const bf16* __restrict__ X, int xld,
    const bf16* __restrict__ W, int wld,
    int kslice, float* __restrict__ out, int ldc,
    bf16* Xs, bf16* Ws)
{
    int tid = threadIdx.x;
    int warp = tid >> 5, lane = tid & 31;
    int wm = warp & 1, wn = warp >> 1;
    int grp = lane >> 2, tg = lane & 3;
    uint4* Xs4 = (uint4*)Xs;
    uint4* Ws4 = (uint4*)Ws;

    float acc[4][4];
    #pragma unroll
    for (int nt = 0; nt < 4; nt++)
        #pragma unroll
        for (int q = 0; q < 4; q++) acc[nt][q] = 0.f;

    for (int k0 = 0; k0 < kslice; k0 += 32) {
        #pragma unroll
        for (int u = 0; u < 2; u++) {
            int idx = tid + u*256;
            int row = idx >> 2, c8 = (idx & 3) * 8;
            Ws4[row*5 + (c8 >> 3)] = *(const uint4*)(W + (long)row*wld + k0 + c8);
        }
        if (tid < 128) {
            int row = tid >> 2, c8 = (tid & 3) * 8;
            Xs4[row*5 + (c8 >> 3)] = __ldcg((const uint4*)(X + (long)row*xld + k0 + c8));
        }
        __syncthreads();
        #pragma unroll
        for (int ks = 0; ks < 2; ks++) {
            int kof = ks*16 + tg*2;
            int m0 = wm*16 + grp;
            u32 a0 = *(const u32*)&Xs[m0*40 + kof];
            u32 a1 = *(const u32*)&Xs[(m0+8)*40 + kof];
            u32 a2 = *(const u32*)&Xs[m0*40 + kof + 8];
            u32 a3 = *(const u32*)&Xs[(m0+8)*40 + kof + 8];
            #pragma unroll
            for (int nt = 0; nt < 4; nt++) {
                int n0 = wn*32 + nt*8 + grp;
                u32 b0 = *(const u32*)&Ws[n0*40 + kof];
                u32 b1 = *(const u32*)&Ws[n0*40 + kof + 8];
                mma_bf16(acc[nt][0], acc[nt][1], acc[nt][2], acc[nt][3],
                         a0, a1, a2, a3, b0, b1);
            }
        }
        __syncthreads();
    }
    int m0 = wm*16 + grp;
    #pragma unroll
    for (int nt = 0; nt < 4; nt++) {
        int n = wn*32 + nt*8 + tg*2;
        __stcg((float2*)&out[(long)m0*ldc + n],     make_float2(acc[nt][0], acc[nt][1]));
        __stcg((float2*)&out[(long)(m0+8)*ldc + n], make_float2(acc[nt][2], acc[nt][3]));
    }
}

// =====================================================================
// persistent encoder loop: 64 blocks, 2 barriers per step (R13 exact)
// =====================================================================
__global__ void __launch_bounds__(256, 1)
k_enc_loop(const float* __restrict__ b_f, const float* __restrict__ b_b) {
    __shared__ __align__(16) bf16 Xs[32*40];
    __shared__ __align__(16) bf16 Ws[128*40];
    int bid = blockIdx.x, tid = threadIdx.x;
    unsigned sense = *(volatile unsigned*)&g_bars;

    int dir = bid >> 5, rem = bid & 31, sp = rem >> 4, ct = rem & 15;
    int c0 = ct * 128, k0 = sp * 256;
    const bf16* Whh = (dir ? g_whhbb : g_whhfb) + (long)c0*HH + k0;

    // point-phase element mapping (fixed per thread -> c stays L1-private)
    int pi  = bid*256 + tid;          // 0..16383
    int pdir = pi >> 13;
    int prem = pi & 8191;
    int pb  = prem >> 8;              // /(HH/2)
    int pj  = (prem & 255) * 2;
    float* cbuf = (pdir ? g_cb : g_cf) + pb*HH;
    const float* bias = pdir ? b_b : b_f;

    // init h=0, c=0 (same mapping as point phase)
    {
        __nv_bfloat162 z = __floats2bfloat162_rn(0.f, 0.f);
        stcg_bf2(((pdir ? g_hbb[0] : g_hfb[0]) + pb*HH) + pj, z);
        *(float2*)&cbuf[pj] = make_float2(0.f, 0.f);
    }
    gbar(NB_ENC, sense);

    for (int t = 0; t < TS; t++) {
        // ---- gemm phase: gates_h partial = h @ Whh^T (one tile per block)
        const bf16* X = (dir ? g_hbb[t & 1] : g_hfb[t & 1]) + k0;
        hg32_core(X, HH, Whh, HH, 256, &g_pe[dir][sp][0][0] + c0, 4*HH, Xs, Ws);
        gbar(NB_ENC, sense);

        // ---- point phase
        {
            int pos = pdir ? (TS-1-t) : t;
            const float* gx = &g_gxe[pdir][pos*BB + pb][0];
            float2 g0 = *(const float2*)&bias[0*HH + pj];
            float2 g1 = *(const float2*)&bias[1*HH + pj];
            float2 g2 = *(const float2*)&bias[2*HH + pj];
            float2 g3 = *(const float2*)&bias[3*HH + pj];
            float2 v;
            v = *(const float2*)&gx[0*HH + pj]; g0.x += v.x; g0.y += v.y;
            v = *(const float2*)&gx[1*HH + pj]; g1.x += v.x; g1.y += v.y;
            v = *(const float2*)&gx[2*HH + pj]; g2.x += v.x; g2.y += v.y;
            v = *(const float2*)&gx[3*HH + pj]; g3.x += v.x; g3.y += v.y;
            #pragma unroll
            for (int s = 0; s < 2; s++) {
                const float* p = &g_pe[pdir][s][pb][0];
                v = __ldcg((const float2*)&p[0*HH + pj]); g0.x += v.x; g0.y += v.y;
                v = __ldcg((const float2*)&p[1*HH + pj]); g1.x += v.x; g1.y += v.y;
                v = __ldcg((const float2*)&p[2*HH + pj]); g2.x += v.x; g2.y += v.y;
                v = __ldcg((const float2*)&p[3*HH + pj]); g3.x += v.x; g3.y += v.y;
            }
            float2 cc = *(float2*)&cbuf[pj];
            float2 c, h;
            c.x = sigmoidf(g1.x) * cc.x + sigmoidf(g0.x) * tanhf(g2.x);
            c.y = sigmoidf(g1.y) * cc.y + sigmoidf(g0.y) * tanhf(g2.y);
            h.x = sigmoidf(g3.x) * tanhf(c.x);
            h.y = sigmoidf(g3.y) * tanhf(c.y);
            *(float2*)&cbuf[pj] = c;
            bf16* hnext = (pdir ? g_hbb[(t+1) & 1] : g_hfb[(t+1) & 1]) + pb*HH;
            stcg_bf2(&hnext[pj], __floats2bfloat162_rn(h.x, h.y));
            long oidx = ((long)pos*BB + pb)*DH + pdir*HH + pj;
            *(float2*)&g_enc_out[oidx] = h;
            *(__nv_bfloat162*)&g_enc_outb[oidx] = __floats2bfloat162_rn(h.x, h.y);
        }
        gbar(NB_ENC, sense);
    }
}

// =====================================================================
// persistent decoder loop: 128 blocks, init + 4 barriers per step (R13 exact)
// =====================================================================
__global__ void __launch_bounds__(256, 1)
k_dec_loop(const float* __restrict__ va, const float* __restrict__ b_d) {
    __shared__ __align__(16) bf16 Xs[32*40];
    __shared__ __align__(16) bf16 Ws[128*40];
    __shared__ float s_hq[DH];
    __shared__ float s_sc[TS];
    __shared__ float s_inv;
    int bid = blockIdx.x, tid = threadIdx.x;
    unsigned sense = *(volatile unsigned*)&g_bars;

    // gemm1 tile (blocks 0..79): 40 col-tiles x 2 k-splits, kslice 512
    int g1c0 = (bid % 40) * 128, g1sp = bid / 40, g1k0 = g1sp * 512;
    const bf16* g1W = (g1c0 < 4*DH) ? (g_whhdb + (long)g1c0*DH + g1k0)
                                    : (g_wa1b + (long)(g1c0 - 4*DH)*DH + g1k0);
    // gemm2 tile (all 128 blocks): 32 col-tiles x 4 k-splits, kslice 256
    int g2c0 = (bid & 31) * 128, g2sp = bid >> 5, g2k0 = g2sp * 256;
    const bf16* g2W = g_wih2db + (long)g2c0*DH + g2k0;

    // point/init mapping (fixed -> g_dc stays L1-private)
    int pi = bid*256 + tid;
    int pb = pi >> 9;                  // /(DH/2)
    int pj = (pi & 511) * 2;
    bool pact = pi < BB*DH/2;

    // ---- init: concat encoder final states
    if (pact) {
        __nv_bfloat162 h; float2 c;
        if (pj < HH) {
            h = __floats2bfloat162_rn(__bfloat162float(g_hfb[0][pb*HH + pj]),
                                      __bfloat162float(g_hfb[0][pb*HH + pj + 1]));
            c = make_float2(g_cf[pb*HH + pj], g_cf[pb*HH + pj + 1]);
        } else {
            h = __floats2bfloat162_rn(__bfloat162float(g_hbb[0][pb*HH + pj - HH]),
                                      __bfloat162float(g_hbb[0][pb*HH + pj - HH + 1]));
            c = make_float2(g_cb[pb*HH + pj - HH], g_cb[pb*HH + pj - HH + 1]);
        }
        stcg_bf2(&g_dhb[0][pb*DH + pj], h);
        *(float2*)&g_dc[pb*DH + pj] = c;
    }
    gbar(NB_DEC, sense);

    for (int t = 0; t < TT; t++) {
        // ---- gemm1: [gates_h | hq] = h @ [Whh_d | Wa1]^T
        if (bid < 80) {
            hg32_core(g_dhb[t & 1] + g1k0, DH, g1W, DH, 512,
                      &g_pd1[g1sp][0][0] + g1c0, ND1, Xs, Ws);
        }
        gbar(NB_DEC, sense);

        // ---- attention (blocks 0..31, one per batch row)
        if (bid < BB) {
            int b = bid;
            for (int o = tid; o < DH; o += 256) {
                float v = __ldcg(&g_pd1[0][b][4*DH + o]) + __ldcg(&g_pd1[1][b][4*DH + o]);
                s_hq[o] = v;
            }
            __syncthreads();
            int w = tid >> 5, lane = tid & 31;
            for (int ts = w; ts < TS; ts += 8) {
                const float* ep = g_encproj + ((long)ts*BB + b)*DH;
                float s = 0.f;
                for (int o = lane; o < DH; o += 32) s += va[o] * tanh_fast(s_hq[o] + ep[o]);
                s = warp_sum(s);
                if (lane == 0) s_sc[ts] = s;
            }
            __syncthreads();
            if (tid == 0) {
                float m = -1e30f;
                for (int i = 0; i < TS; i++) m = fmaxf(m, s_sc[i]);
                float s = 0.f;
                for (int i = 0; i < TS; i++) { float e = expf(s_sc[i] - m); s_sc[i] = e; s += e; }
                s_inv = 1.f / s;
            }
            __syncthreads();
            float inv = s_inv;
            for (int o = tid*2; o < DH; o += 512) {     // 256 threads x 2 cols (even o)
                float a0 = 0.f, a1 = 0.f;
                #pragma unroll 4
                for (int ts = 0; ts < TS; ts++) {
                    float2 e = *(const float2*)&g_enc_out[((long)ts*BB + b)*DH + o];
                    a0 += s_sc[ts] * e.x; a1 += s_sc[ts] * e.y;
                }
                stcg_bf2(&g_cvecb[b*DH + o], __floats2bfloat162_rn(a0 * inv, a1 * inv));
            }
        }
        gbar(NB_DEC, sense);

        // ---- gemm2: gates_c = cvec @ Wih2^T
        hg32_core(g_cvecb + g2k0, DH, g2W, DH, 256,
                  &g_pd2[g2sp][0][0] + g2c0, 4*DH, Xs, Ws);
        gbar(NB_DEC, sense);

        // ---- point
        if (pact) {
            const float* gx = &g_gxd[t*BB + pb][0];
            float2 g0 = *(const float2*)&b_d[0*DH + pj];
            float2 g1 = *(const float2*)&b_d[1*DH + pj];
            float2 g2 = *(const float2*)&b_d[2*DH + pj];
            float2 g3 = *(const float2*)&b_d[3*DH + pj];
            float2 v;
            v = *(const float2*)&gx[0*DH + pj]; g0.x += v.x; g0.y += v.y;
            v = *(const float2*)&gx[1*DH + pj]; g1.x += v.x; g1.y += v.y;
            v = *(const float2*)&gx[2*DH + pj]; g2.x += v.x; g2.y += v.y;
            v = *(const float2*)&gx[3*DH + pj]; g3.x += v.x; g3.y += v.y;
            #pragma unroll
            for (int s = 0; s < 2; s++) {
                const float* p1 = &g_pd1[s][pb][0];
                v = __ldcg((const float2*)&p1[0*DH + pj]); g0.x += v.x; g0.y += v.y;
                v = __ldcg((const float2*)&p1[1*DH + pj]); g1.x += v.x; g1.y += v.y;
                v = __ldcg((const float2*)&p1[2*DH + pj]); g2.x += v.x; g2.y += v.y;
                v = __ldcg((const float2*)&p1[3*DH + pj]); g3.x += v.x; g3.y += v.y;
            }
            #pragma unroll
            for (int s = 0; s < 4; s++) {
                const float* p2 = &g_pd2[s][pb][0];
                v = __ldcg((const float2*)&p2[0*DH + pj]); g0.x += v.x; g0.y += v.y;
                v = __ldcg((const float2*)&p2[1*DH + pj]); g1.x += v.x; g1.y += v.y;
                v = __ldcg((const float2*)&p2[2*DH + pj]); g2.x += v.x; g2.y += v.y;
                v = __ldcg((const float2*)&p2[3*DH + pj]); g3.x += v.x; g3.y += v.y;
            }
            long si = (long)pb*DH + pj;
            float2 cc = *(float2*)&g_dc[si];
            float2 c, h;
            c.x = sigmoidf(g1.x) * cc.x + sigmoidf(g0.x) * tanhf(g2.x);
            c.y = sigmoidf(g1.y) * cc.y + sigmoidf(g0.y) * tanhf(g2.y);
            h.x = sigmoidf(g3.x) * tanhf(c.x);
            h.y = sigmoidf(g3.y) * tanhf(c.y);
            *(float2*)&g_dc[si] = c;
            stcg_bf2(&g_dhb[(t+1) & 1][si], __floats2bfloat162_rn(h.x, h.y));
            *(__nv_bfloat162*)&g_hsb[((long)pb*TT + t)*DH + pj] = __floats2bfloat162_rn(h.x, h.y);
        }
        gbar(NB_DEC, sense);
    }
}

// =====================================================================
// bf16 tensor-core GEMM, cp.async double-buffered (STANDALONE — no
// inter-block sync, so the async pipeline is provably safe here):
// C[M,N] = A[M,K] @ B[N,K]^T (+bias, +relu), fp32 C.
// 128x128 block tile, BK=32, 256 threads.
// =====================================================================
__global__ void hgemm_abt(const bf16* __restrict__ A, int lda,
                          const bf16* __restrict__ B, int ldb,
                          const float* __restrict__ bias,
                          float* __restrict__ C, int ldc,
                          int K, int do_relu) {
    __shared__ __align__(16) bf16 As[2*128*40];
    __shared__ __align__(16) bf16 Bs[2*128*40];
    int tid = threadIdx.x;
    int bm = blockIdx.y, bn = blockIdx.x;
    int warp = tid >> 5, lane = tid & 31;
    int wm = warp & 1, wn = warp >> 1;
    int grp = lane >> 2, tg = lane & 3;
    int lr = tid >> 2, lc = (tid & 3) * 8;

    const bf16* Ag = A + (long)bm*128*lda;
    const bf16* Bg = B + (long)bn*128*ldb;
    u32 AsA = (u32)__cvta_generic_to_shared(As);
    u32 BsA = (u32)__cvta_generic_to_shared(Bs);

    float acc[4][4][4];
    #pragma unroll
    for (int mt = 0; mt < 4; mt++)
        #pragma unroll
        for (int nt = 0; nt < 4; nt++)
            #pragma unroll
            for (int q = 0; q < 4; q++) acc[mt][nt][q] = 0.f;

    int niter = K >> 5;
    // prologue: stage 0
    cpa_ca(AsA + (lr*40 + lc)*2,      Ag + (long)lr*lda + lc);
    cpa_ca(AsA + ((lr+64)*40 + lc)*2, Ag + (long)(lr+64)*lda + lc);
    cpa_ca(BsA + (lr*40 + lc)*2,      Bg + (long)lr*ldb + lc);
    cpa_ca(BsA + ((lr+64)*40 + lc)*2, Bg + (long)(lr+64)*ldb + lc);
    CPA_COMMIT();

    for (int i = 0; i < niter; i++) {
        if (i + 1 < niter) {
            int st = (i + 1) & 1, k0 = (i + 1) << 5;
            u32 ab = AsA + st*(128*40*2), bb = BsA + st*(128*40*2);
            cpa_ca(ab + (lr*40 + lc)*2,      Ag + (long)lr*lda + k0 + lc);
            cpa_ca(ab + ((lr+64)*40 + lc)*2, Ag + (long)(lr+64)*lda + k0 + lc);
            cpa_ca(bb + (lr*40 + lc)*2,      Bg + (long)lr*ldb + k0 + lc);
            cpa_ca(bb + ((lr+64)*40 + lc)*2, Bg + (long)(lr+64)*ldb + k0 + lc);
            CPA_COMMIT();
            CPA_WAIT1();
        } else {
            CPA_WAIT0();
        }
        __syncthreads();
        const bf16* Ast = As + (i & 1) * (128*40);
        const bf16* Bst = Bs + (i & 1) * (128*40);
        #pragma unroll
        for (int ks = 0; ks < 2; ks++) {
            int kof = ks*16 + tg*2;
            u32 af[4][4], bf[4][2];
            #pragma unroll
            for (int mt = 0; mt < 4; mt++) {
                int m0 = wm*64 + mt*16 + grp;
                af[mt][0] = *(const u32*)&Ast[(m0    )*40 + kof    ];
                af[mt][1] = *(const u32*)&Ast[(m0 + 8)*40 + kof    ];
                af[mt][2] = *(const u32*)&Ast[(m0    )*40 + kof + 8];
                af[mt][3] = *(const u32*)&Ast[(m0 + 8)*40 + kof + 8];
            }
            #pragma unroll
            for (int nt = 0; nt < 4; nt++) {
                int n0 = wn*32 + nt*8 + grp;
                bf[nt][0] = *(const u32*)&Bst[n0*40 + kof    ];
                bf[nt][1] = *(const u32*)&Bst[n0*40 + kof + 8];
            }
            #pragma unroll
            for (int mt = 0; mt < 4; mt++)
                #pragma unroll
                for (int nt = 0; nt < 4; nt++)
                    mma_bf16(acc[mt][nt][0], acc[mt][nt][1], acc[mt][nt][2], acc[mt][nt][3],
                             af[mt][0], af[mt][1], af[mt][2], af[mt][3],
                             bf[nt][0], bf[nt][1]);
        }
        __syncthreads();
    }

    #pragma unroll
    for (int mt = 0; mt < 4; mt++) {
        long m = (long)bm*128 + wm*64 + mt*16 + grp;
        #pragma unroll
        for (int nt = 0; nt < 4; nt++) {
            int n = bn*128 + wn*32 + nt*8 + tg*2;
            float2 v0 = make_float2(acc[mt][nt][0], acc[mt][nt][1]);
            float2 v1 = make_float2(acc[mt][nt][2], acc[mt][nt][3]);
            if (bias) {
                float2 bb = *(const float2*)&bias[n];
                v0.x += bb.x; v0.y += bb.y; v1.x += bb.x; v1.y += bb.y;
            }
            if (do_relu) {
                v0.x = fmaxf(v0.x, 0.f); v0.y = fmaxf(v0.y, 0.f);
                v1.x = fmaxf(v1.x, 0.f); v1.y = fmaxf(v1.y, 0.f);
            }
            *(float2*)&C[m*ldc + n]     = v0;
            *(float2*)&C[(m+8)*ldc + n] = v1;
        }
    }
}

// ---------------- per-row max / logsumexp (online, one pass, float4) -------
__device__ __forceinline__ void ms_combine(float& m, float& s, float m2, float s2) {
    float M = fmaxf(m, m2);
    s = s * expf(m - M) + s2 * expf(m2 - M);
    m = M;
}
__global__ void k_row_reduce(const float* __restrict__ C) {
    __shared__ float sm[8], ss[8];
    int row = blockIdx.x, tid = threadIdx.x;
    const float4* p4 = (const float4*)(C + (long)row * VV);
    float m = -1e30f, s = 0.f;
    for (int n = tid; n < VV/4; n += 256) {
        float4 x = p4[n];
        float lm = fmaxf(fmaxf(x.x, x.y), fmaxf(x.z, x.w));
        float M = fmaxf(m, lm);
        s = s * expf(m - M)
          + expf(x.x - M) + expf(x.y - M) + expf(x.z - M) + expf(x.w - M);
        m = M;
    }
    #pragma unroll
    for (int o = 16; o; o >>= 1) {
        float m2 = __shfl_xor_sync(0xffffffffu, m, o);
        float s2 = __shfl_xor_sync(0xffffffffu, s, o);
        ms_combine(m, s, m2, s2);
    }
    int w = tid >> 5;
    if ((tid & 31) == 0) { sm[w] = m; ss[w] = s; }
    __syncthreads();
    if (tid == 0) {
        m = sm[0]; s = ss[0];
        for (int i = 1; i < 8; i++) ms_combine(m, s, sm[i], ss[i]);
        g_rowmax[row] = m;
        g_rowlse[row] = logf(s);
    }
}

// ---------------- apply log_softmax in place (float4) ----------------
__global__ void k_lsm(float* __restrict__ C) {
    long i = (long)blockIdx.x * blockDim.x + threadIdx.x;   // float4 index, exact grid
    int row = (int)(i / (VV/4));
    float sub = g_rowmax[row] + g_rowlse[row];
    float4* p = (float4*)C;
    float4 v = p[i];
    v.x -= sub; v.y -= sub; v.z -= sub; v.w -= sub;
    p[i] = v;
}

// ---------------- launch ----------------
extern "C" void kernel_launch(void* const* d_in, const int* in_sizes, int n_in,
                              void* d_out, int out_size) {
    const int*   inp     = (const int*)  d_in[0];
    const int*   tar     = (const int*)  d_in[1];
    const float* enc_emb = (const float*)d_in[2];
    const float* dec_emb = (const float*)d_in[3];
    const float* Wih_f   = (const float*)d_in[4];
    const float* Whh_f   = (const float*)d_in[5];
    const float* b_f     = (const float*)d_in[6];
    const float* Wih_b   = (const float*)d_in[7];
    const float* Whh_b   = (const float*)d_in[8];
    const float* b_b     = (const float*)d_in[9];
    const float* Wa      = (const float*)d_in[10];
    const float* va      = (const float*)d_in[11];
    const float* Wih_d   = (const float*)d_in[12];
    const float* Whh_d   = (const float*)d_in[13];
    const float* b_d     = (const float*)d_in[14];
    const float* Wout    = (const float*)d_in[15];
    const float* bout    = (const float*)d_in[16];
    float* out = (float*)d_out;

    static bf16 *sp_embsrc=nullptr, *sp_embtgt, *sp_wihfb, *sp_wihbb,
                *sp_wih1db, *sp_wih2db, *sp_whhdb, *sp_wa1b, *sp_wa2b, *sp_woutb,
                *sp_encoutb, *sp_hsb, *sp_whhfb, *sp_whhbb;
    static float *sp_gxe, *sp_gxd, *sp_encproj;
    if (!sp_embsrc) {
        cudaGetSymbolAddress((void**)&sp_embsrc,  g_emb_srcb);
        cudaGetSymbolAddress((void**)&sp_embtgt,  g_emb_tgtb);
        cudaGetSymbolAddress((void**)&sp_wihfb,   g_wihfb);
        cudaGetSymbolAddress((void**)&sp_wihbb,   g_wihbb);
        cudaGetSymbolAddress((void**)&sp_whhfb,   g_whhfb);
        cudaGetSymbolAddress((void**)&sp_whhbb,   g_whhbb);
        cudaGetSymbolAddress((void**)&sp_wih1db,  g_wih1db);
        cudaGetSymbolAddress((void**)&sp_wih2db,  g_wih2db);
        cudaGetSymbolAddress((void**)&sp_whhdb,   g_whhdb);
        cudaGetSymbolAddress((void**)&sp_wa1b,    g_wa1b);
        cudaGetSymbolAddress((void**)&sp_wa2b,    g_wa2b);
        cudaGetSymbolAddress((void**)&sp_woutb,   g_woutb);
        cudaGetSymbolAddress((void**)&sp_encoutb, g_enc_outb);
        cudaGetSymbolAddress((void**)&sp_hsb,     g_hsb);
        cudaGetSymbolAddress((void**)&sp_gxe,     g_gxe);
        cudaGetSymbolAddress((void**)&sp_gxd,     g_gxd);
        cudaGetSymbolAddress((void**)&sp_encproj, g_encproj);
    }

    // embeddings + weight conversions
    k_embed<<<(2*TS*BB*EE)/256, 256>>>(inp, tar, enc_emb, dec_emb);
    k_cvt_contig<<<(4*HH*EE/4)/256, 256>>>(Wih_f, sp_wihfb);
    k_cvt_contig<<<(4*HH*HH/4)/256, 256>>>(Whh_f, sp_whhfb);
    k_cvt_contig<<<(4*HH*EE/4)/256, 256>>>(Wih_b, sp_wihbb);
    k_cvt_contig<<<(4*HH*HH/4)/256, 256>>>(Whh_b, sp_whhbb);
    k_cvt_contig<<<(int)(((long)4*DH*DH/4)/256), 256>>>(Whh_d, sp_whhdb);
    k_cvt_contig<<<(int)(((long)VV*DH/4)/256), 256>>>(Wout, sp_woutb);
    k_cvt_strided<<<(int)(((long)4*DH*EE/2)/256), 256>>>(Wih_d, sp_wih1db, 1536, 0, EE);
    k_cvt_strided<<<(int)(((long)4*DH*DH/2)/256), 256>>>(Wih_d, sp_wih2db, 1536, EE, DH);
    k_cvt_strided<<<((DH*DH)/2)/256, 256>>>(Wa, sp_wa1b, 2*DH, 0,  DH);
    k_cvt_strided<<<((DH*DH)/2)/256, 256>>>(Wa, sp_wa2b, 2*DH, DH, DH);

    // precompute input-side gate contributions (bf16 MMA, async-pipelined)
    hgemm_abt<<<dim3((4*HH)/128, (TS*BB)/128), 256>>>(sp_embsrc, EE, sp_wihfb, EE,
                                                      nullptr, sp_gxe, 4*HH, EE, 0);
    hgemm_abt<<<dim3((4*HH)/128, (TS*BB)/128), 256>>>(sp_embsrc, EE, sp_wihbb, EE,
                                                      nullptr, sp_gxe + (long)TS*BB*4*HH, 4*HH, EE, 0);
    hgemm_abt<<<dim3((4*DH)/128, (TT*BB)/128), 256>>>(sp_embtgt, EE, sp_wih1db, EE,
                                                      nullptr, sp_gxd, 4*DH, EE, 0);

    // encoder BiLSTM: one persistent kernel (init + 64 steps)
    k_enc_loop<<<NB_ENC, 256>>>(b_f, b_b);

    // attention precompute: enc_proj = enc_out @ Wa2^T
    hgemm_abt<<<dim3(DH/128, (TS*BB)/128), 256>>>(sp_encoutb, DH, sp_wa2b, DH,
                                                  nullptr, sp_encproj, DH, DH, 0);

    // decoder: one persistent kernel (init + 64 steps)
    k_dec_loop<<<NB_DEC, 256>>>(va, b_d);

    // output projection + relu (bf16 MMA), then log_softmax
    hgemm_abt<<<dim3(VV/128, MOUT/128), 256>>>(sp_hsb, DH, sp_woutb, DH,
                                               bout, out, VV, DH, 1);
    k_row_reduce<<<MOUT, 256>>>(out);
    k_lsm<<<(int)(((long)MOUT*VV/4)/256), 256>>>(out);
}